// round 7
// baseline (speedup 1.0000x reference)
#include <cuda_runtime.h>
#include <cuda_bf16.h>
#include <cstdint>
#include <math.h>

// Problem constants
#define BB 8
#define CC 512
#define NN 4096
#define MM 1024

// ---------------------------------------------------------------------------
// Scratch: bf16 hi/lo plane pairs for every GEMM operand (no cudaMalloc).
// ---------------------------------------------------------------------------
__device__ __nv_bfloat16 g_TupH[(size_t)BB * NN * CC];  // pcd_up^T  [B][N][C]
__device__ __nv_bfloat16 g_TupL[(size_t)BB * NN * CC];
__device__ __nv_bfloat16 g_TdnH[(size_t)BB * MM * CC];  // pcd_down^T [B][M][C]
__device__ __nv_bfloat16 g_TdnL[(size_t)BB * MM * CC];
__device__ __nv_bfloat16 g_WqH[CC * CC], g_WqL[CC * CC];
__device__ __nv_bfloat16 g_WkH[CC * CC], g_WkL[CC * CC];
__device__ __nv_bfloat16 g_WvH[CC * CC], g_WvL[CC * CC];
__device__ __nv_bfloat16 g_WsH[CC * CC], g_WsL[CC * CC];
__device__ __nv_bfloat16 g_QtH[(size_t)BB * NN * CC];   // Q^T [B][N][C]
__device__ __nv_bfloat16 g_QtL[(size_t)BB * NN * CC];
__device__ __nv_bfloat16 g_KtH[(size_t)BB * MM * CC];   // K^T [B][M][C]
__device__ __nv_bfloat16 g_KtL[(size_t)BB * MM * CC];
__device__ __nv_bfloat16 g_VH [(size_t)BB * CC * MM];   // V [B][C][M]
__device__ __nv_bfloat16 g_VL [(size_t)BB * CC * MM];
__device__ float         g_E  [(size_t)BB * NN * MM];   // energy fp32
__device__ __nv_bfloat16 g_PH [(size_t)BB * NN * MM];   // attention planes
__device__ __nv_bfloat16 g_PL [(size_t)BB * NN * MM];

// ---------------------------------------------------------------------------
// helpers
// ---------------------------------------------------------------------------
__device__ __forceinline__ uint32_t smem_u32(const void* p) {
    uint32_t a;
    asm("{ .reg .u64 t; cvta.to.shared.u64 t, %1; cvt.u32.u64 %0, t; }"
        : "=r"(a) : "l"(p));
    return a;
}

__device__ __forceinline__ void split_bf16(float x, __nv_bfloat16& h, __nv_bfloat16& l) {
    h = __float2bfloat16_rn(x);
    l = __float2bfloat16_rn(x - __bfloat162float(h));
}

__device__ __forceinline__ void mma_bf16(float* c, const uint32_t* a,
                                         uint32_t b0, uint32_t b1) {
    asm volatile(
        "mma.sync.aligned.m16n8k16.row.col.f32.bf16.bf16.f32 "
        "{%0,%1,%2,%3}, {%4,%5,%6,%7}, {%8,%9}, {%0,%1,%2,%3};"
        : "+f"(c[0]), "+f"(c[1]), "+f"(c[2]), "+f"(c[3])
        : "r"(a[0]), "r"(a[1]), "r"(a[2]), "r"(a[3]), "r"(b0), "r"(b1));
}

__device__ __forceinline__ void ldsm4(uint32_t& r0, uint32_t& r1,
                                      uint32_t& r2, uint32_t& r3, uint32_t addr) {
    asm volatile("ldmatrix.sync.aligned.m8n8.x4.shared.b16 {%0,%1,%2,%3}, [%4];"
                 : "=r"(r0), "=r"(r1), "=r"(r2), "=r"(r3) : "r"(addr));
}

#define CP16(dst, src) \
    asm volatile("cp.async.cg.shared.global [%0], [%1], 16;" :: "r"(dst), "l"(src))
#define CP_COMMIT() asm volatile("cp.async.commit_group;" ::: "memory")
#define CP_WAIT2()  asm volatile("cp.async.wait_group 2;" ::: "memory")
#define CP_WAIT1()  asm volatile("cp.async.wait_group 1;" ::: "memory")
#define CP_WAIT0()  asm volatile("cp.async.wait_group 0;" ::: "memory")

// ---------------------------------------------------------------------------
// transpose + split: in fp32 [rows, cols] per batch -> hi/lo bf16 [cols, rows]
// ---------------------------------------------------------------------------
__global__ void __launch_bounds__(256) transpose_split_kernel(
    const float* __restrict__ in, __nv_bfloat16* __restrict__ oh,
    __nv_bfloat16* __restrict__ ol, int rows, int cols)
{
    __shared__ float t[32][33];
    const int b = blockIdx.z;
    in += (size_t)b * rows * cols;
    oh += (size_t)b * rows * cols;
    ol += (size_t)b * rows * cols;
    const int r0 = blockIdx.y * 32, c0 = blockIdx.x * 32;
    const int tx = threadIdx.x & 31, ty = threadIdx.x >> 5;
    #pragma unroll
    for (int i = 0; i < 32; i += 8)
        t[ty + i][tx] = in[(size_t)(r0 + ty + i) * cols + c0 + tx];
    __syncthreads();
    #pragma unroll
    for (int i = 0; i < 32; i += 8) {
        float v = t[tx][ty + i];
        __nv_bfloat16 h, l;
        split_bf16(v, h, l);
        size_t o = (size_t)(c0 + ty + i) * rows + r0 + tx;
        oh[o] = h;
        ol[o] = l;
    }
}

// one kernel splits all four weight matrices (blockIdx.y selects)
__global__ void __launch_bounds__(256) split4_kernel(
    const float* __restrict__ W0, const float* __restrict__ W1,
    const float* __restrict__ W2, const float* __restrict__ W3,
    __nv_bfloat16* __restrict__ H0, __nv_bfloat16* __restrict__ L0,
    __nv_bfloat16* __restrict__ H1, __nv_bfloat16* __restrict__ L1,
    __nv_bfloat16* __restrict__ H2, __nv_bfloat16* __restrict__ L2,
    __nv_bfloat16* __restrict__ H3, __nv_bfloat16* __restrict__ L3,
    int n)
{
    int i = blockIdx.x * 256 + threadIdx.x;
    if (i >= n) return;
    const float* W;
    __nv_bfloat16 *H, *L;
    switch (blockIdx.y) {
        case 0:  W = W0; H = H0; L = L0; break;
        case 1:  W = W1; H = H1; L = L1; break;
        case 2:  W = W2; H = H2; L = L2; break;
        default: W = W3; H = H3; L = L3; break;
    }
    __nv_bfloat16 h, l;
    split_bf16(W[i], h, l);
    H[i] = h;
    L[i] = l;
}

// ---------------------------------------------------------------------------
// Tensor-core GEMM, bf16x3 fp32 emulation, pre-split bf16 plane inputs.
//   D[m, n] (CTA tile 64x128) = scale * sum_k A[m][k] * B[n][k]
// OUTMODE: 0 = fp32 store, 1 = fp32 accumulate, 2 = split hi/lo bf16 store.
// 8 warps of 32x32; cp.async 4-stage ring (96 KB), prefetch distance 3,
// ONE __syncthreads per stage. XOR chunk swizzle, 64 B rows.
// ---------------------------------------------------------------------------
#define KT 32
#define APLANE  4096              // 64 rows x 64 B
#define BPLANE  8192              // 128 rows x 64 B
#define STAGE   (2 * APLANE + 2 * BPLANE)   // 24 KB
#define SMEMBYTES (4 * STAGE)               // 96 KB
#define OFF_AH 0
#define OFF_AL APLANE
#define OFF_BH (2 * APLANE)
#define OFF_BL (2 * APLANE + BPLANE)

template<int OUTMODE>
__global__ void __launch_bounds__(256, 2) tc_gemm(
    const __nv_bfloat16* __restrict__ AH, const __nv_bfloat16* __restrict__ AL,
    const __nv_bfloat16* __restrict__ BH, const __nv_bfloat16* __restrict__ BL,
    void* __restrict__ Dp, void* __restrict__ Dp2,
    int lda, int ldb, int ldd,
    size_t strA, size_t strB, size_t strD,
    int Kdim, float scale)
{
    extern __shared__ char smem[];
    const uint32_t sb = smem_u32(smem);

    const int tid  = threadIdx.x;
    const int wid  = tid >> 5;
    const int lane = tid & 31;
    const int g    = lane >> 2;
    const int t4   = lane & 3;
    const int wm   = (wid >> 2) * 32;   // 2 warps along m (64)
    const int wn   = (wid & 3) * 32;    // 4 warps along n (128)

    const int bz = blockIdx.z;
    const int m0 = blockIdx.y * 64;
    const int n0 = blockIdx.x * 128;

    AH += (size_t)bz * strA;  AL += (size_t)bz * strA;
    BH += (size_t)bz * strB;  BL += (size_t)bz * strB;

    float acc[2][4][4] = {};
    const int nstages = Kdim / KT;

    // ---- cp.async one KT stage into ring buffer buf ----
    auto stage_load = [&](int k0, int buf) {
        const uint32_t sbase = sb + buf * STAGE;
        const int row = tid >> 2;         // 0..63
        const int kc  = tid & 3;          // 16B chunk
        // A planes: 64 rows, one chunk per thread per plane
        {
            uint32_t doff = (uint32_t)(row * 64 + ((kc ^ ((row >> 1) & 3)) << 4));
            size_t goff = (size_t)(m0 + row) * lda + k0 + kc * 8;
            CP16(sbase + OFF_AH + doff, AH + goff);
            CP16(sbase + OFF_AL + doff, AL + goff);
        }
        // B planes: 128 rows, two chunks per thread per plane
        #pragma unroll
        for (int i = 0; i < 2; i++) {
            int r = row + i * 64;
            uint32_t doff = (uint32_t)(r * 64 + ((kc ^ ((r >> 1) & 3)) << 4));
            size_t goff = (size_t)(n0 + r) * ldb + k0 + kc * 8;
            CP16(sbase + OFF_BH + doff, BH + goff);
            CP16(sbase + OFF_BL + doff, BL + goff);
        }
    };

    // ---- one KT stage of MMAs from ring buffer buf ----
    auto compute = [&](int buf) {
        const uint32_t bAh = sb + buf * STAGE + OFF_AH;
        const uint32_t bAl = sb + buf * STAGE + OFF_AL;
        const uint32_t bBh = sb + buf * STAGE + OFF_BH;
        const uint32_t bBl = sb + buf * STAGE + OFF_BL;
        const int t = lane >> 3, ri = lane & 7;
        #pragma unroll
        for (int kp = 0; kp < 2; kp++) {
            uint32_t ah[2][4], al[2][4];
            #pragma unroll
            for (int ma = 0; ma < 2; ma++) {
                int row = wm + ma * 16 + (t & 1) * 8 + ri;
                int c   = 2 * kp + (t >> 1);
                uint32_t off = (uint32_t)(row * 32 + ((c ^ ((row >> 1) & 3)) << 3)) * 2;
                ldsm4(ah[ma][0], ah[ma][1], ah[ma][2], ah[ma][3], bAh + off);
                ldsm4(al[ma][0], al[ma][1], al[ma][2], al[ma][3], bAl + off);
            }
            #pragma unroll
            for (int np = 0; np < 2; np++) {
                int row = wn + np * 16 + (t >> 1) * 8 + ri;
                int c   = 2 * kp + (t & 1);
                uint32_t off = (uint32_t)(row * 32 + ((c ^ ((row >> 1) & 3)) << 3)) * 2;
                uint32_t bh[4], bl[4];
                ldsm4(bh[0], bh[1], bh[2], bh[3], bBh + off);
                ldsm4(bl[0], bl[1], bl[2], bl[3], bBl + off);
                #pragma unroll
                for (int sub = 0; sub < 2; sub++) {
                    int na = np * 2 + sub;
                    #pragma unroll
                    for (int ma = 0; ma < 2; ma++) {
                        mma_bf16(acc[ma][na], ah[ma], bh[sub * 2], bh[sub * 2 + 1]);
                        mma_bf16(acc[ma][na], ah[ma], bl[sub * 2], bl[sub * 2 + 1]);
                        mma_bf16(acc[ma][na], al[ma], bh[sub * 2], bh[sub * 2 + 1]);
                    }
                }
            }
        }
    };

    // ---- software pipeline: 4-deep ring, distance 3, one barrier/stage ----
    stage_load(0, 0);       CP_COMMIT();
    stage_load(KT, 1);      CP_COMMIT();
    stage_load(2 * KT, 2);  CP_COMMIT();

    for (int s = 0; s < nstages; s++) {
        if (s + 2 < nstages)      CP_WAIT2();
        else if (s + 1 < nstages) CP_WAIT1();
        else                      CP_WAIT0();
        __syncthreads();    // publish stage s; fences recycled buffer
        if (s + 3 < nstages) {
            // writes buffer computed at stage s-1 — all warps past it (barrier)
            stage_load((s + 3) * KT, (s + 3) & 3);
            CP_COMMIT();
        }
        compute(s & 3);
    }

    // ---- epilogue ----
    #pragma unroll
    for (int ma = 0; ma < 2; ma++) {
        #pragma unroll
        for (int na = 0; na < 4; na++) {
            const int r0 = m0 + wm + ma * 16 + g;
            const int cb = n0 + wn + na * 8 + 2 * t4;
            float v[4] = {acc[ma][na][0] * scale, acc[ma][na][1] * scale,
                          acc[ma][na][2] * scale, acc[ma][na][3] * scale};
            if (OUTMODE == 2) {
                __nv_bfloat16* Dh = (__nv_bfloat16*)Dp + (size_t)bz * strD;
                __nv_bfloat16* Dl = (__nv_bfloat16*)Dp2 + (size_t)bz * strD;
                #pragma unroll
                for (int hrow = 0; hrow < 2; hrow++) {
                    size_t o = (size_t)(r0 + hrow * 8) * ldd + cb;
                    __nv_bfloat16 h0, l0, h1, l1;
                    split_bf16(v[hrow * 2 + 0], h0, l0);
                    split_bf16(v[hrow * 2 + 1], h1, l1);
                    __nv_bfloat162 ph; ph.x = h0; ph.y = h1;
                    __nv_bfloat162 pl; pl.x = l0; pl.y = l1;
                    *(__nv_bfloat162*)&Dh[o] = ph;
                    *(__nv_bfloat162*)&Dl[o] = pl;
                }
            } else {
                float* D = (float*)Dp + (size_t)bz * strD;
                #pragma unroll
                for (int hrow = 0; hrow < 2; hrow++) {
                    float* p = &D[(size_t)(r0 + hrow * 8) * ldd + cb];
                    float2 w = make_float2(v[hrow * 2], v[hrow * 2 + 1]);
                    if (OUTMODE == 1) {
                        float2 o = *(const float2*)p;
                        w.x += o.x; w.y += o.y;
                    }
                    *(float2*)p = w;
                }
            }
        }
    }
}

// ---------------------------------------------------------------------------
// Softmax over last dim (M=1024): read fp32 E, write split hi/lo bf16 P.
// ---------------------------------------------------------------------------
__global__ void __launch_bounds__(256) softmax_split_kernel(
    const float* __restrict__ E, __nv_bfloat16* __restrict__ PH,
    __nv_bfloat16* __restrict__ PL)
{
    const size_t rb = (size_t)blockIdx.x * MM;
    const float4* row = (const float4*)(E + rb);
    const int t = threadIdx.x;
    float4 v = row[t];

    __shared__ float rmax[8];
    __shared__ float rsum[8];

    float mx = fmaxf(fmaxf(v.x, v.y), fmaxf(v.z, v.w));
    #pragma unroll
    for (int o = 16; o > 0; o >>= 1)
        mx = fmaxf(mx, __shfl_xor_sync(0xffffffffu, mx, o));
    if ((t & 31) == 0) rmax[t >> 5] = mx;
    __syncthreads();
    mx = rmax[0];
    #pragma unroll
    for (int i = 1; i < 8; i++) mx = fmaxf(mx, rmax[i]);

    float e[4];
    e[0] = __expf(v.x - mx);
    e[1] = __expf(v.y - mx);
    e[2] = __expf(v.z - mx);
    e[3] = __expf(v.w - mx);
    float s = e[0] + e[1] + e[2] + e[3];
    #pragma unroll
    for (int o = 16; o > 0; o >>= 1)
        s += __shfl_xor_sync(0xffffffffu, s, o);
    if ((t & 31) == 0) rsum[t >> 5] = s;
    __syncthreads();
    s = rsum[0];
    #pragma unroll
    for (int i = 1; i < 8; i++) s += rsum[i];

    const float inv = 1.0f / s;
    __nv_bfloat16 h[4], l[4];
    #pragma unroll
    for (int i = 0; i < 4; i++) split_bf16(e[i] * inv, h[i], l[i]);
    *(uint2*)&PH[rb + t * 4] = *(uint2*)h;
    *(uint2*)&PL[rb + t * 4] = *(uint2*)l;
}

// ---------------------------------------------------------------------------
// Launch
// ---------------------------------------------------------------------------
extern "C" void kernel_launch(void* const* d_in, const int* in_sizes, int n_in,
                              void* d_out, int out_size)
{
    const float* pcd_up   = (const float*)d_in[0];
    const float* pcd_down = (const float*)d_in[1];
    const float* Wq       = (const float*)d_in[2];
    const float* Wk       = (const float*)d_in[3];
    const float* Wv       = (const float*)d_in[4];
    const float* Wskip    = (const float*)d_in[5];
    float* out = (float*)d_out;

    __nv_bfloat16 *TupH, *TupL, *TdnH, *TdnL, *WqH, *WqL, *WkH, *WkL;
    __nv_bfloat16 *WvH, *WvL, *WsH, *WsL, *QtH, *QtL, *KtH, *KtL, *VH, *VL, *PH, *PL;
    float* E;
    cudaGetSymbolAddress((void**)&TupH, g_TupH);
    cudaGetSymbolAddress((void**)&TupL, g_TupL);
    cudaGetSymbolAddress((void**)&TdnH, g_TdnH);
    cudaGetSymbolAddress((void**)&TdnL, g_TdnL);
    cudaGetSymbolAddress((void**)&WqH, g_WqH);
    cudaGetSymbolAddress((void**)&WqL, g_WqL);
    cudaGetSymbolAddress((void**)&WkH, g_WkH);
    cudaGetSymbolAddress((void**)&WkL, g_WkL);
    cudaGetSymbolAddress((void**)&WvH, g_WvH);
    cudaGetSymbolAddress((void**)&WvL, g_WvL);
    cudaGetSymbolAddress((void**)&WsH, g_WsH);
    cudaGetSymbolAddress((void**)&WsL, g_WsL);
    cudaGetSymbolAddress((void**)&QtH, g_QtH);
    cudaGetSymbolAddress((void**)&QtL, g_QtL);
    cudaGetSymbolAddress((void**)&KtH, g_KtH);
    cudaGetSymbolAddress((void**)&KtL, g_KtL);
    cudaGetSymbolAddress((void**)&VH, g_VH);
    cudaGetSymbolAddress((void**)&VL, g_VL);
    cudaGetSymbolAddress((void**)&PH, g_PH);
    cudaGetSymbolAddress((void**)&PL, g_PL);
    cudaGetSymbolAddress((void**)&E, g_E);

    static bool attr_done = false;
    if (!attr_done) {
        cudaFuncSetAttribute(tc_gemm<0>, cudaFuncAttributeMaxDynamicSharedMemorySize, SMEMBYTES);
        cudaFuncSetAttribute(tc_gemm<1>, cudaFuncAttributeMaxDynamicSharedMemorySize, SMEMBYTES);
        cudaFuncSetAttribute(tc_gemm<2>, cudaFuncAttributeMaxDynamicSharedMemorySize, SMEMBYTES);
        attr_done = true;
    }

    const float rscale = 0.04419417382415922f;  // 1/sqrt(512)
    const size_t sNC = (size_t)NN * CC;
    const size_t sMC = (size_t)MM * CC;
    const size_t sE  = (size_t)NN * MM;

    // 0) transpose + split inputs (2 launches); split weights (1 launch)
    transpose_split_kernel<<<dim3(NN / 32, CC / 32, BB), 256>>>(pcd_up, TupH, TupL, CC, NN);
    transpose_split_kernel<<<dim3(MM / 32, CC / 32, BB), 256>>>(pcd_down, TdnH, TdnL, CC, MM);
    split4_kernel<<<dim3(CC * CC / 256, 4), 256>>>(
        Wq, Wk, Wv, Wskip, WqH, WqL, WkH, WkL, WvH, WvL, WsH, WsL, CC * CC);

    // 1) Qt[n][o] = sum_c Tup[n][c] Wq[o][c]          (M=N, N=C)
    tc_gemm<2><<<dim3(CC / 128, NN / 64, BB), 256, SMEMBYTES>>>(
        TupH, TupL, WqH, WqL, QtH, QtL, CC, CC, CC, sNC, 0, sNC, CC, 1.0f);
    // 2) Kt[m][o] = sum_c Tdn[m][c] Wk[o][c]          (M=M, N=C)
    tc_gemm<2><<<dim3(CC / 128, MM / 64, BB), 256, SMEMBYTES>>>(
        TdnH, TdnL, WkH, WkL, KtH, KtL, CC, CC, CC, sMC, 0, sMC, CC, 1.0f);
    // 3) V[o][m] = sum_c Wv[o][c] Tdn[m][c]           (M=C, N=M)  <- ncu launch #6
    tc_gemm<2><<<dim3(MM / 128, CC / 64, BB), 256, SMEMBYTES>>>(
        WvH, WvL, TdnH, TdnL, VH, VL, CC, CC, MM, 0, sMC, sMC, CC, 1.0f);
    // 4) out[o][n] = sum_c Wskip[o][c] Tup[n][c]      (M=C, N=N)
    tc_gemm<0><<<dim3(NN / 128, CC / 64, BB), 256, SMEMBYTES>>>(
        WsH, WsL, TupH, TupL, out, nullptr, CC, CC, NN, 0, sNC, sNC, CC, 1.0f);

    // 5) E[n][m] = rscale * sum_c Qt[n][c] Kt[m][c]   (M=N, N=M)
    tc_gemm<0><<<dim3(MM / 128, NN / 64, BB), 256, SMEMBYTES>>>(
        QtH, QtL, KtH, KtL, E, nullptr, CC, CC, MM, sNC, sMC, sE, CC, rscale);

    // 6) softmax over M -> split P planes
    softmax_split_kernel<<<BB * NN, 256>>>(E, PH, PL);

    // 7) out[c][n] += sum_m V[c][m] P[n][m]           (M=C, N=N, K=M)
    tc_gemm<1><<<dim3(NN / 128, CC / 64, BB), 256, SMEMBYTES>>>(
        VH, VL, PH, PL, out, nullptr, MM, MM, NN, sMC, sE, sNC, MM, 1.0f);
}

// round 8
// speedup vs baseline: 1.9108x; 1.9108x over previous
#include <cuda_runtime.h>
#include <cuda_fp16.h>
#include <cstdint>
#include <math.h>

// Problem constants
#define BB 8
#define CC 512
#define NN 4096
#define MM 1024

// ---------------------------------------------------------------------------
// Scratch (no cudaMalloc): fp16 operand planes; fp32 energy; P split hi/lo.
// ---------------------------------------------------------------------------
__device__ __half g_Tup16[(size_t)BB * NN * CC];  // pcd_up^T  [B][N][C]
__device__ __half g_Tdn16[(size_t)BB * MM * CC];  // pcd_down^T [B][M][C]
__device__ __half g_Wq16[CC * CC], g_Wk16[CC * CC];
__device__ __half g_Wv16[CC * CC], g_Ws16[CC * CC];
__device__ __half g_Qt16[(size_t)BB * NN * CC];   // Q^T [B][N][C]
__device__ __half g_Kt16[(size_t)BB * MM * CC];   // K^T [B][M][C]
__device__ __half g_V16 [(size_t)BB * CC * MM];   // V [B][C][M]
__device__ float  g_E   [(size_t)BB * NN * MM];   // energy fp32
__device__ __half g_PH  [(size_t)BB * NN * MM];   // attention hi
__device__ __half g_PL  [(size_t)BB * NN * MM];   // attention lo

// ---------------------------------------------------------------------------
// helpers
// ---------------------------------------------------------------------------
__device__ __forceinline__ uint32_t smem_u32(const void* p) {
    uint32_t a;
    asm("{ .reg .u64 t; cvta.to.shared.u64 t, %1; cvt.u32.u64 %0, t; }"
        : "=r"(a) : "l"(p));
    return a;
}

__device__ __forceinline__ void mma_f16(float* c, const uint32_t* a,
                                        uint32_t b0, uint32_t b1) {
    asm volatile(
        "mma.sync.aligned.m16n8k16.row.col.f32.f16.f16.f32 "
        "{%0,%1,%2,%3}, {%4,%5,%6,%7}, {%8,%9}, {%0,%1,%2,%3};"
        : "+f"(c[0]), "+f"(c[1]), "+f"(c[2]), "+f"(c[3])
        : "r"(a[0]), "r"(a[1]), "r"(a[2]), "r"(a[3]), "r"(b0), "r"(b1));
}

__device__ __forceinline__ void ldsm4(uint32_t& r0, uint32_t& r1,
                                      uint32_t& r2, uint32_t& r3, uint32_t addr) {
    asm volatile("ldmatrix.sync.aligned.m8n8.x4.shared.b16 {%0,%1,%2,%3}, [%4];"
                 : "=r"(r0), "=r"(r1), "=r"(r2), "=r"(r3) : "r"(addr));
}

#define CP16(dst, src) \
    asm volatile("cp.async.cg.shared.global [%0], [%1], 16;" :: "r"(dst), "l"(src))
#define CP_COMMIT() asm volatile("cp.async.commit_group;" ::: "memory")
#define CP_WAIT2()  asm volatile("cp.async.wait_group 2;" ::: "memory")
#define CP_WAIT1()  asm volatile("cp.async.wait_group 1;" ::: "memory")
#define CP_WAIT0()  asm volatile("cp.async.wait_group 0;" ::: "memory")

// ---------------------------------------------------------------------------
// transpose + convert: fp32 [rows, cols] per batch -> fp16 [cols, rows]
// ---------------------------------------------------------------------------
__global__ void __launch_bounds__(256) transpose_cvt_kernel(
    const float* __restrict__ in, __half* __restrict__ oh, int rows, int cols)
{
    __shared__ float t[32][33];
    const int b = blockIdx.z;
    in += (size_t)b * rows * cols;
    oh += (size_t)b * rows * cols;
    const int r0 = blockIdx.y * 32, c0 = blockIdx.x * 32;
    const int tx = threadIdx.x & 31, ty = threadIdx.x >> 5;
    #pragma unroll
    for (int i = 0; i < 32; i += 8)
        t[ty + i][tx] = in[(size_t)(r0 + ty + i) * cols + c0 + tx];
    __syncthreads();
    #pragma unroll
    for (int i = 0; i < 32; i += 8)
        oh[(size_t)(c0 + ty + i) * rows + r0 + tx] = __float2half_rn(t[tx][ty + i]);
}

// one kernel converts all four weight matrices (blockIdx.y selects)
__global__ void __launch_bounds__(256) cvt4_kernel(
    const float* __restrict__ W0, const float* __restrict__ W1,
    const float* __restrict__ W2, const float* __restrict__ W3,
    __half* __restrict__ H0, __half* __restrict__ H1,
    __half* __restrict__ H2, __half* __restrict__ H3, int n)
{
    int i = blockIdx.x * 256 + threadIdx.x;
    if (i >= n) return;
    const float* W;
    __half* H;
    switch (blockIdx.y) {
        case 0:  W = W0; H = H0; break;
        case 1:  W = W1; H = H1; break;
        case 2:  W = W2; H = H2; break;
        default: W = W3; H = H3; break;
    }
    H[i] = __float2half_rn(W[i]);
}

// ---------------------------------------------------------------------------
// Tensor-core fp16 GEMM.
//   D[m, n] (CTA tile 128x128) = scale * sum_k A[m][k] * B[n][k]
// OUTMODE: 0 = fp32 store, 1 = fp32 accumulate, 2 = fp16 store.
// BSPLIT: B has hi+lo fp16 planes (2 MMAs/slice) — used for the P operand.
// 8 warps of 32x64; cp.async 4-stage ring, prefetch distance 3,
// one __syncthreads per stage. XOR chunk swizzle, 64 B rows.
// ---------------------------------------------------------------------------
#define KT 32
#define PL16 8192                 // 128 rows x 64 B plane

template<int OUTMODE, bool BSPLIT>
__global__ void __launch_bounds__(256, 2) tc_gemm(
    const __half* __restrict__ AH, const __half* __restrict__ BH,
    const __half* __restrict__ BL,
    void* __restrict__ Dp,
    int lda, int ldb, int ldd,
    size_t strA, size_t strB, size_t strD,
    int Kdim, float scale)
{
    extern __shared__ char smem[];
    const uint32_t sb = smem_u32(smem);
    const uint32_t STAGE = BSPLIT ? 3 * PL16 : 2 * PL16;

    const int tid  = threadIdx.x;
    const int wid  = tid >> 5;
    const int lane = tid & 31;
    const int g    = lane >> 2;
    const int t4   = lane & 3;
    const int wm   = (wid >> 1) * 32;   // 4 warps along m (128)
    const int wn   = (wid & 1) * 64;    // 2 warps along n (128)

    const int bz = blockIdx.z;
    const int m0 = blockIdx.y * 128;
    const int n0 = blockIdx.x * 128;

    AH += (size_t)bz * strA;
    BH += (size_t)bz * strB;
    if (BSPLIT) BL += (size_t)bz * strB;

    float acc[2][8][4] = {};
    const int nstages = Kdim / KT;

    // ---- cp.async one KT stage into ring buffer buf ----
    auto stage_load = [&](int k0, int buf) {
        const uint32_t sbase = sb + buf * STAGE;
        #pragma unroll
        for (int i = 0; i < 2; i++) {
            int f = tid + i * 256;          // 0..511
            int row = f >> 2, kc = f & 3;
            uint32_t doff = (uint32_t)(row * 64 + ((kc ^ ((row >> 1) & 3)) << 4));
            size_t aoff = (size_t)(m0 + row) * lda + k0 + kc * 8;
            size_t boff = (size_t)(n0 + row) * ldb + k0 + kc * 8;
            CP16(sbase + doff,            AH + aoff);
            CP16(sbase + PL16 + doff,     BH + boff);
            if (BSPLIT) CP16(sbase + 2 * PL16 + doff, BL + boff);
        }
    };

    // ---- one KT stage of MMAs from ring buffer buf ----
    auto compute = [&](int buf) {
        const uint32_t bA  = sb + buf * STAGE;
        const uint32_t bBh = bA + PL16;
        const uint32_t bBl = bA + 2 * PL16;
        const int t = lane >> 3, ri = lane & 7;
        #pragma unroll
        for (int kp = 0; kp < 2; kp++) {
            uint32_t af[2][4];
            #pragma unroll
            for (int ma = 0; ma < 2; ma++) {
                int row = wm + ma * 16 + (t & 1) * 8 + ri;
                int c   = 2 * kp + (t >> 1);
                uint32_t off = (uint32_t)(row * 32 + ((c ^ ((row >> 1) & 3)) << 3)) * 2;
                ldsm4(af[ma][0], af[ma][1], af[ma][2], af[ma][3], bA + off);
            }
            #pragma unroll
            for (int np = 0; np < 4; np++) {
                int row = wn + np * 16 + (t >> 1) * 8 + ri;
                int c   = 2 * kp + (t & 1);
                uint32_t off = (uint32_t)(row * 32 + ((c ^ ((row >> 1) & 3)) << 3)) * 2;
                uint32_t bh[4];
                ldsm4(bh[0], bh[1], bh[2], bh[3], bBh + off);
                uint32_t bl[4];
                if (BSPLIT) ldsm4(bl[0], bl[1], bl[2], bl[3], bBl + off);
                #pragma unroll
                for (int sub = 0; sub < 2; sub++) {
                    int na = np * 2 + sub;
                    #pragma unroll
                    for (int ma = 0; ma < 2; ma++) {
                        mma_f16(acc[ma][na], af[ma], bh[sub * 2], bh[sub * 2 + 1]);
                        if (BSPLIT)
                            mma_f16(acc[ma][na], af[ma], bl[sub * 2], bl[sub * 2 + 1]);
                    }
                }
            }
        }
    };

    // ---- software pipeline: 4-deep ring, distance 3, one barrier/stage ----
    stage_load(0, 0);       CP_COMMIT();
    stage_load(KT, 1);      CP_COMMIT();
    stage_load(2 * KT, 2);  CP_COMMIT();

    for (int s = 0; s < nstages; s++) {
        if (s + 2 < nstages)      CP_WAIT2();
        else if (s + 1 < nstages) CP_WAIT1();
        else                      CP_WAIT0();
        __syncthreads();    // publish stage s; fences recycled buffer
        if (s + 3 < nstages) {
            stage_load((s + 3) * KT, (s + 3) & 3);
            CP_COMMIT();
        }
        compute(s & 3);
    }

    // ---- epilogue ----
    #pragma unroll
    for (int ma = 0; ma < 2; ma++) {
        #pragma unroll
        for (int na = 0; na < 8; na++) {
            const int r0 = m0 + wm + ma * 16 + g;
            const int cb = n0 + wn + na * 8 + 2 * t4;
            float v[4] = {acc[ma][na][0] * scale, acc[ma][na][1] * scale,
                          acc[ma][na][2] * scale, acc[ma][na][3] * scale};
            if (OUTMODE == 2) {
                __half* Dh = (__half*)Dp + (size_t)bz * strD;
                #pragma unroll
                for (int hrow = 0; hrow < 2; hrow++) {
                    size_t o = (size_t)(r0 + hrow * 8) * ldd + cb;
                    __half2 p;
                    p.x = __float2half_rn(v[hrow * 2 + 0]);
                    p.y = __float2half_rn(v[hrow * 2 + 1]);
                    *(__half2*)&Dh[o] = p;
                }
            } else {
                float* D = (float*)Dp + (size_t)bz * strD;
                #pragma unroll
                for (int hrow = 0; hrow < 2; hrow++) {
                    float* p = &D[(size_t)(r0 + hrow * 8) * ldd + cb];
                    float2 w = make_float2(v[hrow * 2], v[hrow * 2 + 1]);
                    if (OUTMODE == 1) {
                        float2 o = *(const float2*)p;
                        w.x += o.x; w.y += o.y;
                    }
                    *(float2*)p = w;
                }
            }
        }
    }
}

// ---------------------------------------------------------------------------
// Softmax over last dim (M=1024): read fp32 E, write fp16 hi/lo planes of P.
// ---------------------------------------------------------------------------
__global__ void __launch_bounds__(256) softmax_split_kernel(
    const float* __restrict__ E, __half* __restrict__ PH,
    __half* __restrict__ PL)
{
    const size_t rb = (size_t)blockIdx.x * MM;
    const float4* row = (const float4*)(E + rb);
    const int t = threadIdx.x;
    float4 v = row[t];

    __shared__ float rmax[8];
    __shared__ float rsum[8];

    float mx = fmaxf(fmaxf(v.x, v.y), fmaxf(v.z, v.w));
    #pragma unroll
    for (int o = 16; o > 0; o >>= 1)
        mx = fmaxf(mx, __shfl_xor_sync(0xffffffffu, mx, o));
    if ((t & 31) == 0) rmax[t >> 5] = mx;
    __syncthreads();
    mx = rmax[0];
    #pragma unroll
    for (int i = 1; i < 8; i++) mx = fmaxf(mx, rmax[i]);

    float e[4];
    e[0] = __expf(v.x - mx);
    e[1] = __expf(v.y - mx);
    e[2] = __expf(v.z - mx);
    e[3] = __expf(v.w - mx);
    float s = e[0] + e[1] + e[2] + e[3];
    #pragma unroll
    for (int o = 16; o > 0; o >>= 1)
        s += __shfl_xor_sync(0xffffffffu, s, o);
    if ((t & 31) == 0) rsum[t >> 5] = s;
    __syncthreads();
    s = rsum[0];
    #pragma unroll
    for (int i = 1; i < 8; i++) s += rsum[i];

    const float inv = 1.0f / s;
    __half h[4], l[4];
    #pragma unroll
    for (int i = 0; i < 4; i++) {
        float p = e[i] * inv;
        h[i] = __float2half_rn(p);
        l[i] = __float2half_rn(p - __half2float(h[i]));
    }
    *(uint2*)&PH[rb + t * 4] = *(uint2*)h;
    *(uint2*)&PL[rb + t * 4] = *(uint2*)l;
}

// ---------------------------------------------------------------------------
// Launch
// ---------------------------------------------------------------------------
extern "C" void kernel_launch(void* const* d_in, const int* in_sizes, int n_in,
                              void* d_out, int out_size)
{
    const float* pcd_up   = (const float*)d_in[0];
    const float* pcd_down = (const float*)d_in[1];
    const float* Wq       = (const float*)d_in[2];
    const float* Wk       = (const float*)d_in[3];
    const float* Wv       = (const float*)d_in[4];
    const float* Wskip    = (const float*)d_in[5];
    float* out = (float*)d_out;

    __half *Tup, *Tdn, *Wq16, *Wk16, *Wv16, *Ws16, *Qt, *Kt, *V, *PH, *PL;
    float* E;
    cudaGetSymbolAddress((void**)&Tup, g_Tup16);
    cudaGetSymbolAddress((void**)&Tdn, g_Tdn16);
    cudaGetSymbolAddress((void**)&Wq16, g_Wq16);
    cudaGetSymbolAddress((void**)&Wk16, g_Wk16);
    cudaGetSymbolAddress((void**)&Wv16, g_Wv16);
    cudaGetSymbolAddress((void**)&Ws16, g_Ws16);
    cudaGetSymbolAddress((void**)&Qt, g_Qt16);
    cudaGetSymbolAddress((void**)&Kt, g_Kt16);
    cudaGetSymbolAddress((void**)&V, g_V16);
    cudaGetSymbolAddress((void**)&PH, g_PH);
    cudaGetSymbolAddress((void**)&PL, g_PL);
    cudaGetSymbolAddress((void**)&E, g_E);

    static bool attr_done = false;
    if (!attr_done) {
        cudaFuncSetAttribute(tc_gemm<0, false>,
                             cudaFuncAttributeMaxDynamicSharedMemorySize, 4 * 2 * PL16);
        cudaFuncSetAttribute(tc_gemm<2, false>,
                             cudaFuncAttributeMaxDynamicSharedMemorySize, 4 * 2 * PL16);
        cudaFuncSetAttribute(tc_gemm<1, true>,
                             cudaFuncAttributeMaxDynamicSharedMemorySize, 4 * 3 * PL16);
        attr_done = true;
    }

    const float rscale = 0.04419417382415922f;  // 1/sqrt(512)
    const size_t sNC = (size_t)NN * CC;
    const size_t sMC = (size_t)MM * CC;
    const size_t sE  = (size_t)NN * MM;
    const int S2 = 4 * 2 * PL16;   // 64 KB
    const int S3 = 4 * 3 * PL16;   // 96 KB

    // 0) transpose+cvt inputs; cvt weights
    transpose_cvt_kernel<<<dim3(NN / 32, CC / 32, BB), 256>>>(pcd_up, Tup, CC, NN);
    transpose_cvt_kernel<<<dim3(MM / 32, CC / 32, BB), 256>>>(pcd_down, Tdn, CC, MM);
    cvt4_kernel<<<dim3(CC * CC / 256, 4), 256>>>(
        Wq, Wk, Wv, Wskip, Wq16, Wk16, Wv16, Ws16, CC * CC);

    // 1) Qt[n][o] = sum_c Tup[n][c] Wq[o][c]        -> fp16
    tc_gemm<2, false><<<dim3(CC / 128, NN / 128, BB), 256, S2>>>(
        Tup, Wq16, nullptr, Qt, CC, CC, CC, sNC, 0, sNC, CC, 1.0f);
    // 2) Kt[m][o] = sum_c Tdn[m][c] Wk[o][c]        -> fp16
    tc_gemm<2, false><<<dim3(CC / 128, MM / 128, BB), 256, S2>>>(
        Tdn, Wk16, nullptr, Kt, CC, CC, CC, sMC, 0, sMC, CC, 1.0f);
    // 3) V[o][m] = sum_c Wv[o][c] Tdn[m][c]         -> fp16
    tc_gemm<2, false><<<dim3(MM / 128, CC / 128, BB), 256, S2>>>(
        Wv16, Tdn, nullptr, V, CC, CC, MM, 0, sMC, sMC, CC, 1.0f);
    // 4) out[o][n] = sum_c Wskip[o][c] Tup[n][c]    -> fp32 out
    tc_gemm<0, false><<<dim3(NN / 128, CC / 128, BB), 256, S2>>>(
        Ws16, Tup, nullptr, out, CC, CC, NN, 0, sNC, sNC, CC, 1.0f);

    // 5) E[n][m] = rscale * sum_c Qt[n][c] Kt[m][c] -> fp32
    tc_gemm<0, false><<<dim3(MM / 128, NN / 128, BB), 256, S2>>>(
        Qt, Kt, nullptr, E, CC, CC, MM, sNC, sMC, sE, CC, rscale);

    // 6) softmax over M -> P hi/lo fp16 planes
    softmax_split_kernel<<<BB * NN, 256>>>(E, PH, PL);

    // 7) out[c][n] += sum_m V[c][m] P[n][m]  (B = P split hi/lo)
    tc_gemm<1, true><<<dim3(NN / 128, CC / 128, BB), 256, S3>>>(
        V, PH, PL, out, MM, MM, NN, sMC, sE, sNC, MM, 1.0f);
}

// round 9
// speedup vs baseline: 2.2112x; 1.1572x over previous
#include <cuda_runtime.h>
#include <cuda_fp16.h>
#include <cstdint>
#include <math.h>

// Problem constants
#define BB 8
#define CC 512
#define NN 4096
#define MM 1024

// ---------------------------------------------------------------------------
// Scratch (no cudaMalloc): fp16 operand planes; fp16 energy / attention.
// ---------------------------------------------------------------------------
__device__ __half g_Tup16[(size_t)BB * NN * CC];  // pcd_up^T  [B][N][C]
__device__ __half g_Tdn16[(size_t)BB * MM * CC];  // pcd_down^T [B][M][C]
__device__ __half g_Wq16[CC * CC], g_Wk16[CC * CC];
__device__ __half g_Wv16[CC * CC], g_Ws16[CC * CC];
__device__ __half g_Qt16[(size_t)BB * NN * CC];   // Q^T [B][N][C]
__device__ __half g_Kt16[(size_t)BB * MM * CC];   // K^T [B][M][C]
__device__ __half g_V16 [(size_t)BB * CC * MM];   // V [B][C][M]
__device__ __half g_E   [(size_t)BB * NN * MM];   // energy fp16 (scaled)
__device__ __half g_P   [(size_t)BB * NN * MM];   // attention fp16

// ---------------------------------------------------------------------------
// helpers
// ---------------------------------------------------------------------------
__device__ __forceinline__ uint32_t smem_u32(const void* p) {
    uint32_t a;
    asm("{ .reg .u64 t; cvta.to.shared.u64 t, %1; cvt.u32.u64 %0, t; }"
        : "=r"(a) : "l"(p));
    return a;
}

__device__ __forceinline__ void mma_f16(float* c, const uint32_t* a,
                                        uint32_t b0, uint32_t b1) {
    asm volatile(
        "mma.sync.aligned.m16n8k16.row.col.f32.f16.f16.f32 "
        "{%0,%1,%2,%3}, {%4,%5,%6,%7}, {%8,%9}, {%0,%1,%2,%3};"
        : "+f"(c[0]), "+f"(c[1]), "+f"(c[2]), "+f"(c[3])
        : "r"(a[0]), "r"(a[1]), "r"(a[2]), "r"(a[3]), "r"(b0), "r"(b1));
}

__device__ __forceinline__ void ldsm4(uint32_t& r0, uint32_t& r1,
                                      uint32_t& r2, uint32_t& r3, uint32_t addr) {
    asm volatile("ldmatrix.sync.aligned.m8n8.x4.shared.b16 {%0,%1,%2,%3}, [%4];"
                 : "=r"(r0), "=r"(r1), "=r"(r2), "=r"(r3) : "r"(addr));
}

#define CP16(dst, src) \
    asm volatile("cp.async.cg.shared.global [%0], [%1], 16;" :: "r"(dst), "l"(src))
#define CP_COMMIT() asm volatile("cp.async.commit_group;" ::: "memory")
#define CP_WAIT2()  asm volatile("cp.async.wait_group 2;" ::: "memory")
#define CP_WAIT1()  asm volatile("cp.async.wait_group 1;" ::: "memory")
#define CP_WAIT0()  asm volatile("cp.async.wait_group 0;" ::: "memory")

// ---------------------------------------------------------------------------
// transpose + convert: fp32 [rows, cols] per batch -> fp16 [cols, rows]
// ---------------------------------------------------------------------------
__global__ void __launch_bounds__(256) transpose_cvt_kernel(
    const float* __restrict__ in, __half* __restrict__ oh, int rows, int cols)
{
    __shared__ float t[32][33];
    const int b = blockIdx.z;
    in += (size_t)b * rows * cols;
    oh += (size_t)b * rows * cols;
    const int r0 = blockIdx.y * 32, c0 = blockIdx.x * 32;
    const int tx = threadIdx.x & 31, ty = threadIdx.x >> 5;
    #pragma unroll
    for (int i = 0; i < 32; i += 8)
        t[ty + i][tx] = in[(size_t)(r0 + ty + i) * cols + c0 + tx];
    __syncthreads();
    #pragma unroll
    for (int i = 0; i < 32; i += 8)
        oh[(size_t)(c0 + ty + i) * rows + r0 + tx] = __float2half_rn(t[tx][ty + i]);
}

// one kernel converts all four weight matrices (blockIdx.y selects)
__global__ void __launch_bounds__(256) cvt4_kernel(
    const float* __restrict__ W0, const float* __restrict__ W1,
    const float* __restrict__ W2, const float* __restrict__ W3,
    __half* __restrict__ H0, __half* __restrict__ H1,
    __half* __restrict__ H2, __half* __restrict__ H3, int n)
{
    int i = blockIdx.x * 256 + threadIdx.x;
    if (i >= n) return;
    const float* W;
    __half* H;
    switch (blockIdx.y) {
        case 0:  W = W0; H = H0; break;
        case 1:  W = W1; H = H1; break;
        case 2:  W = W2; H = H2; break;
        default: W = W3; H = H3; break;
    }
    H[i] = __float2half_rn(W[i]);
}

// ---------------------------------------------------------------------------
// Tensor-core fp16 GEMM.
//   D[m, n] (CTA tile 128x128) = scale * sum_k A[m][k] * B[n][k]
// OUTMODE: 0 = fp32 store, 1 = fp32 accumulate, 2 = fp16 store.
// 8 warps of 32x64; cp.async 4-stage ring (64 KB), prefetch distance 3,
// one __syncthreads per stage. XOR chunk swizzle, 64 B rows.
// ---------------------------------------------------------------------------
#define KT 32
#define PL16 8192                 // 128 rows x 64 B plane
#define STAGE (2 * PL16)
#define SMEMBYTES (4 * STAGE)     // 64 KB

template<int OUTMODE>
__global__ void __launch_bounds__(256, 2) tc_gemm(
    const __half* __restrict__ AH, const __half* __restrict__ BH,
    void* __restrict__ Dp,
    int lda, int ldb, int ldd,
    size_t strA, size_t strB, size_t strD,
    int Kdim, float scale)
{
    extern __shared__ char smem[];
    const uint32_t sb = smem_u32(smem);

    const int tid  = threadIdx.x;
    const int wid  = tid >> 5;
    const int lane = tid & 31;
    const int g    = lane >> 2;
    const int t4   = lane & 3;
    const int wm   = (wid >> 1) * 32;   // 4 warps along m (128)
    const int wn   = (wid & 1) * 64;    // 2 warps along n (128)

    const int bz = blockIdx.z;
    const int m0 = blockIdx.y * 128;
    const int n0 = blockIdx.x * 128;

    AH += (size_t)bz * strA;
    BH += (size_t)bz * strB;

    float acc[2][8][4] = {};
    const int nstages = Kdim / KT;

    // ---- cp.async one KT stage into ring buffer buf ----
    auto stage_load = [&](int k0, int buf) {
        const uint32_t sbase = sb + buf * STAGE;
        #pragma unroll
        for (int i = 0; i < 2; i++) {
            int f = tid + i * 256;          // 0..511
            int row = f >> 2, kc = f & 3;
            uint32_t doff = (uint32_t)(row * 64 + ((kc ^ ((row >> 1) & 3)) << 4));
            size_t aoff = (size_t)(m0 + row) * lda + k0 + kc * 8;
            size_t boff = (size_t)(n0 + row) * ldb + k0 + kc * 8;
            CP16(sbase + doff,        AH + aoff);
            CP16(sbase + PL16 + doff, BH + boff);
        }
    };

    // ---- one KT stage of MMAs from ring buffer buf ----
    auto compute = [&](int buf) {
        const uint32_t bA  = sb + buf * STAGE;
        const uint32_t bB  = bA + PL16;
        const int t = lane >> 3, ri = lane & 7;
        #pragma unroll
        for (int kp = 0; kp < 2; kp++) {
            uint32_t af[2][4];
            #pragma unroll
            for (int ma = 0; ma < 2; ma++) {
                int row = wm + ma * 16 + (t & 1) * 8 + ri;
                int c   = 2 * kp + (t >> 1);
                uint32_t off = (uint32_t)(row * 32 + ((c ^ ((row >> 1) & 3)) << 3)) * 2;
                ldsm4(af[ma][0], af[ma][1], af[ma][2], af[ma][3], bA + off);
            }
            #pragma unroll
            for (int np = 0; np < 4; np++) {
                int row = wn + np * 16 + (t >> 1) * 8 + ri;
                int c   = 2 * kp + (t & 1);
                uint32_t off = (uint32_t)(row * 32 + ((c ^ ((row >> 1) & 3)) << 3)) * 2;
                uint32_t bf[4];
                ldsm4(bf[0], bf[1], bf[2], bf[3], bB + off);
                #pragma unroll
                for (int sub = 0; sub < 2; sub++) {
                    int na = np * 2 + sub;
                    #pragma unroll
                    for (int ma = 0; ma < 2; ma++)
                        mma_f16(acc[ma][na], af[ma], bf[sub * 2], bf[sub * 2 + 1]);
                }
            }
        }
    };

    // ---- software pipeline: 4-deep ring, distance 3, one barrier/stage ----
    stage_load(0, 0);       CP_COMMIT();
    stage_load(KT, 1);      CP_COMMIT();
    stage_load(2 * KT, 2);  CP_COMMIT();

    for (int s = 0; s < nstages; s++) {
        if (s + 2 < nstages)      CP_WAIT2();
        else if (s + 1 < nstages) CP_WAIT1();
        else                      CP_WAIT0();
        __syncthreads();    // publish stage s; fences recycled buffer
        if (s + 3 < nstages) {
            stage_load((s + 3) * KT, (s + 3) & 3);
            CP_COMMIT();
        }
        compute(s & 3);
    }

    // ---- epilogue ----
    #pragma unroll
    for (int ma = 0; ma < 2; ma++) {
        #pragma unroll
        for (int na = 0; na < 8; na++) {
            const int r0 = m0 + wm + ma * 16 + g;
            const int cb = n0 + wn + na * 8 + 2 * t4;
            float v[4] = {acc[ma][na][0] * scale, acc[ma][na][1] * scale,
                          acc[ma][na][2] * scale, acc[ma][na][3] * scale};
            if (OUTMODE == 2) {
                __half* Dh = (__half*)Dp + (size_t)bz * strD;
                #pragma unroll
                for (int hrow = 0; hrow < 2; hrow++) {
                    size_t o = (size_t)(r0 + hrow * 8) * ldd + cb;
                    __half2 p;
                    p.x = __float2half_rn(v[hrow * 2 + 0]);
                    p.y = __float2half_rn(v[hrow * 2 + 1]);
                    *(__half2*)&Dh[o] = p;
                }
            } else {
                float* D = (float*)Dp + (size_t)bz * strD;
                #pragma unroll
                for (int hrow = 0; hrow < 2; hrow++) {
                    float* p = &D[(size_t)(r0 + hrow * 8) * ldd + cb];
                    float2 w = make_float2(v[hrow * 2], v[hrow * 2 + 1]);
                    if (OUTMODE == 1) {
                        float2 o = *(const float2*)p;
                        w.x += o.x; w.y += o.y;
                    }
                    *(float2*)p = w;
                }
            }
        }
    }
}

// ---------------------------------------------------------------------------
// Softmax over last dim (M=1024): read fp16 E, write fp16 P.
// One CTA of 256 per row; 4 halves per thread.
// ---------------------------------------------------------------------------
__global__ void __launch_bounds__(256) softmax_kernel(
    const __half* __restrict__ E, __half* __restrict__ P)
{
    const size_t rb = (size_t)blockIdx.x * MM;
    const int t = threadIdx.x;
    __half hv[4];
    *(uint2*)hv = *(const uint2*)&E[rb + t * 4];
    float v[4] = {__half2float(hv[0]), __half2float(hv[1]),
                  __half2float(hv[2]), __half2float(hv[3])};

    __shared__ float rmax[8];
    __shared__ float rsum[8];

    float mx = fmaxf(fmaxf(v[0], v[1]), fmaxf(v[2], v[3]));
    #pragma unroll
    for (int o = 16; o > 0; o >>= 1)
        mx = fmaxf(mx, __shfl_xor_sync(0xffffffffu, mx, o));
    if ((t & 31) == 0) rmax[t >> 5] = mx;
    __syncthreads();
    mx = rmax[0];
    #pragma unroll
    for (int i = 1; i < 8; i++) mx = fmaxf(mx, rmax[i]);

    float e[4];
    #pragma unroll
    for (int i = 0; i < 4; i++) e[i] = __expf(v[i] - mx);
    float s = e[0] + e[1] + e[2] + e[3];
    #pragma unroll
    for (int o = 16; o > 0; o >>= 1)
        s += __shfl_xor_sync(0xffffffffu, s, o);
    if ((t & 31) == 0) rsum[t >> 5] = s;
    __syncthreads();
    s = rsum[0];
    #pragma unroll
    for (int i = 1; i < 8; i++) s += rsum[i];

    const float inv = 1.0f / s;
    __half h[4];
    #pragma unroll
    for (int i = 0; i < 4; i++) h[i] = __float2half_rn(e[i] * inv);
    *(uint2*)&P[rb + t * 4] = *(uint2*)h;
}

// ---------------------------------------------------------------------------
// Launch
// ---------------------------------------------------------------------------
extern "C" void kernel_launch(void* const* d_in, const int* in_sizes, int n_in,
                              void* d_out, int out_size)
{
    const float* pcd_up   = (const float*)d_in[0];
    const float* pcd_down = (const float*)d_in[1];
    const float* Wq       = (const float*)d_in[2];
    const float* Wk       = (const float*)d_in[3];
    const float* Wv       = (const float*)d_in[4];
    const float* Wskip    = (const float*)d_in[5];
    float* out = (float*)d_out;

    __half *Tup, *Tdn, *Wq16, *Wk16, *Wv16, *Ws16, *Qt, *Kt, *V, *E, *P;
    cudaGetSymbolAddress((void**)&Tup, g_Tup16);
    cudaGetSymbolAddress((void**)&Tdn, g_Tdn16);
    cudaGetSymbolAddress((void**)&Wq16, g_Wq16);
    cudaGetSymbolAddress((void**)&Wk16, g_Wk16);
    cudaGetSymbolAddress((void**)&Wv16, g_Wv16);
    cudaGetSymbolAddress((void**)&Ws16, g_Ws16);
    cudaGetSymbolAddress((void**)&Qt, g_Qt16);
    cudaGetSymbolAddress((void**)&Kt, g_Kt16);
    cudaGetSymbolAddress((void**)&V, g_V16);
    cudaGetSymbolAddress((void**)&E, g_E);
    cudaGetSymbolAddress((void**)&P, g_P);

    static bool attr_done = false;
    if (!attr_done) {
        cudaFuncSetAttribute(tc_gemm<0>,
                             cudaFuncAttributeMaxDynamicSharedMemorySize, SMEMBYTES);
        cudaFuncSetAttribute(tc_gemm<1>,
                             cudaFuncAttributeMaxDynamicSharedMemorySize, SMEMBYTES);
        cudaFuncSetAttribute(tc_gemm<2>,
                             cudaFuncAttributeMaxDynamicSharedMemorySize, SMEMBYTES);
        attr_done = true;
    }

    const float rscale = 0.04419417382415922f;  // 1/sqrt(512)
    const size_t sNC = (size_t)NN * CC;
    const size_t sMC = (size_t)MM * CC;
    const size_t sE  = (size_t)NN * MM;

    // 0) transpose+cvt inputs; cvt weights
    transpose_cvt_kernel<<<dim3(NN / 32, CC / 32, BB), 256>>>(pcd_up, Tup, CC, NN);
    transpose_cvt_kernel<<<dim3(MM / 32, CC / 32, BB), 256>>>(pcd_down, Tdn, CC, MM);
    cvt4_kernel<<<dim3(CC * CC / 256, 4), 256>>>(
        Wq, Wk, Wv, Wskip, Wq16, Wk16, Wv16, Ws16, CC * CC);

    // 1) Qt[n][o] = sum_c Tup[n][c] Wq[o][c]        -> fp16
    tc_gemm<2><<<dim3(CC / 128, NN / 128, BB), 256, SMEMBYTES>>>(
        Tup, Wq16, Qt, CC, CC, CC, sNC, 0, sNC, CC, 1.0f);
    // 2) Kt[m][o] = sum_c Tdn[m][c] Wk[o][c]        -> fp16
    tc_gemm<2><<<dim3(CC / 128, MM / 128, BB), 256, SMEMBYTES>>>(
        Tdn, Wk16, Kt, CC, CC, CC, sMC, 0, sMC, CC, 1.0f);
    // 3) V[o][m] = sum_c Wv[o][c] Tdn[m][c]         -> fp16
    tc_gemm<2><<<dim3(MM / 128, CC / 128, BB), 256, SMEMBYTES>>>(
        Wv16, Tdn, V, CC, CC, MM, 0, sMC, sMC, CC, 1.0f);
    // 4) out[o][n] = sum_c Wskip[o][c] Tup[n][c]    -> fp32 out
    tc_gemm<0><<<dim3(NN / 128, CC / 128, BB), 256, SMEMBYTES>>>(
        Ws16, Tup, out, CC, CC, NN, 0, sNC, sNC, CC, 1.0f);

    // 5) E[n][m] = rscale * sum_c Qt[n][c] Kt[m][c] -> fp16 (scaled)
    tc_gemm<2><<<dim3(MM / 128, NN / 128, BB), 256, SMEMBYTES>>>(
        Qt, Kt, E, CC, CC, MM, sNC, sMC, sE, CC, rscale);

    // 6) softmax over M (fp16 in, fp16 out)
    softmax_kernel<<<BB * NN, 256>>>(E, P);

    // 7) out[c][n] += sum_m V[c][m] P[n][m]
    tc_gemm<1><<<dim3(NN / 128, CC / 128, BB), 256, SMEMBYTES>>>(
        V, P, out, MM, MM, NN, sMC, sE, sNC, MM, 1.0f);
}

// round 10
// speedup vs baseline: 2.5460x; 1.1514x over previous
#include <cuda_runtime.h>
#include <cuda_fp16.h>
#include <cstdint>
#include <math.h>

// Problem constants
#define BB 8
#define CC 512
#define NN 4096
#define MM 1024

// ---------------------------------------------------------------------------
// Scratch (no cudaMalloc): fp16 operand planes; fp16 energy / attention.
// ---------------------------------------------------------------------------
__device__ __half g_Tup16[(size_t)BB * NN * CC];  // pcd_up^T  [B][N][C]
__device__ __half g_Tdn16[(size_t)BB * MM * CC];  // pcd_down^T [B][M][C]
__device__ __half g_Wq16[CC * CC], g_Wk16[CC * CC];
__device__ __half g_Wv16[CC * CC], g_Ws16[CC * CC];
__device__ __half g_Qt16[(size_t)BB * NN * CC];   // Q^T [B][N][C]
__device__ __half g_Kt16[(size_t)BB * MM * CC];   // K^T [B][M][C]
__device__ __half g_V16 [(size_t)BB * CC * MM];   // V [B][C][M]
__device__ __half g_E   [(size_t)BB * NN * MM];   // energy fp16 (scaled)
__device__ __half g_P   [(size_t)BB * NN * MM];   // attention fp16

// ---------------------------------------------------------------------------
// helpers
// ---------------------------------------------------------------------------
__device__ __forceinline__ uint32_t smem_u32(const void* p) {
    uint32_t a;
    asm("{ .reg .u64 t; cvta.to.shared.u64 t, %1; cvt.u32.u64 %0, t; }"
        : "=r"(a) : "l"(p));
    return a;
}

__device__ __forceinline__ void mma_f16(float* c, const uint32_t* a,
                                        uint32_t b0, uint32_t b1) {
    asm volatile(
        "mma.sync.aligned.m16n8k16.row.col.f32.f16.f16.f32 "
        "{%0,%1,%2,%3}, {%4,%5,%6,%7}, {%8,%9}, {%0,%1,%2,%3};"
        : "+f"(c[0]), "+f"(c[1]), "+f"(c[2]), "+f"(c[3])
        : "r"(a[0]), "r"(a[1]), "r"(a[2]), "r"(a[3]), "r"(b0), "r"(b1));
}

__device__ __forceinline__ void ldsm4(uint32_t& r0, uint32_t& r1,
                                      uint32_t& r2, uint32_t& r3, uint32_t addr) {
    asm volatile("ldmatrix.sync.aligned.m8n8.x4.shared.b16 {%0,%1,%2,%3}, [%4];"
                 : "=r"(r0), "=r"(r1), "=r"(r2), "=r"(r3) : "r"(addr));
}

#define CP16(dst, src) \
    asm volatile("cp.async.cg.shared.global [%0], [%1], 16;" :: "r"(dst), "l"(src))
#define CP_COMMIT() asm volatile("cp.async.commit_group;" ::: "memory")
#define CP_WAIT1()  asm volatile("cp.async.wait_group 1;" ::: "memory")
#define CP_WAIT0()  asm volatile("cp.async.wait_group 0;" ::: "memory")

// ---------------------------------------------------------------------------
// transpose + convert: fp32 [rows, cols] per batch -> fp16 [cols, rows]
// ---------------------------------------------------------------------------
__global__ void __launch_bounds__(256) transpose_cvt_kernel(
    const float* __restrict__ in, __half* __restrict__ oh, int rows, int cols)
{
    __shared__ float t[32][33];
    const int b = blockIdx.z;
    in += (size_t)b * rows * cols;
    oh += (size_t)b * rows * cols;
    const int r0 = blockIdx.y * 32, c0 = blockIdx.x * 32;
    const int tx = threadIdx.x & 31, ty = threadIdx.x >> 5;
    #pragma unroll
    for (int i = 0; i < 32; i += 8)
        t[ty + i][tx] = in[(size_t)(r0 + ty + i) * cols + c0 + tx];
    __syncthreads();
    #pragma unroll
    for (int i = 0; i < 32; i += 8)
        oh[(size_t)(c0 + ty + i) * rows + r0 + tx] = __float2half_rn(t[tx][ty + i]);
}

// one kernel converts all four weight matrices (blockIdx.y selects)
__global__ void __launch_bounds__(256) cvt4_kernel(
    const float* __restrict__ W0, const float* __restrict__ W1,
    const float* __restrict__ W2, const float* __restrict__ W3,
    __half* __restrict__ H0, __half* __restrict__ H1,
    __half* __restrict__ H2, __half* __restrict__ H3, int n)
{
    int i = blockIdx.x * 256 + threadIdx.x;
    if (i >= n) return;
    const float* W;
    __half* H;
    switch (blockIdx.y) {
        case 0:  W = W0; H = H0; break;
        case 1:  W = W1; H = H1; break;
        case 2:  W = W2; H = H2; break;
        default: W = W3; H = H3; break;
    }
    H[i] = __float2half_rn(W[i]);
}

// ---------------------------------------------------------------------------
// Shared GEMM tile body.
//   D[m, n] (CTA tile 128x128) = scale * sum_k A[m][k] * B[n][k]
// outmode: 0 = fp32 store, 1 = fp32 accumulate, 2 = fp16 store.
// KT=64; 3-stage cp.async ring (96 KB); one __syncthreads per stage.
// Rows of 128 B, 8-chunk XOR swizzle: phys16B = kc ^ (row & 7).
// 8 warps of 32x64.
// ---------------------------------------------------------------------------
#define KT 64
#define PL 16384                   // 128 rows x 128 B plane
#define STAGEB (2 * PL)            // 32 KB
#define SMEMBYTES (3 * STAGEB)     // 96 KB

__device__ __forceinline__ void gemm_tile(
    const __half* __restrict__ AH, const __half* __restrict__ BH,
    void* __restrict__ Dp,
    int lda, int ldb, int ldd,
    int Kdim, float scale, int outmode,
    int m0, int n0, char* smem)
{
    const uint32_t sb = smem_u32(smem);
    const int tid  = threadIdx.x;
    const int wid  = tid >> 5;
    const int lane = tid & 31;
    const int g    = lane >> 2;
    const int t4   = lane & 3;
    const int wm   = (wid >> 1) * 32;   // 4 warps along m (128)
    const int wn   = (wid & 1) * 64;    // 2 warps along n (128)

    float acc[2][8][4] = {};
    const int nstages = Kdim / KT;

    // ---- cp.async one KT stage into ring buffer buf ----
    auto stage_load = [&](int k0, int buf) {
        const uint32_t sbase = sb + buf * STAGEB;
        #pragma unroll
        for (int i = 0; i < 4; i++) {
            int f = tid + i * 256;          // 0..1023
            int row = f >> 3, kc = f & 7;
            uint32_t doff = (uint32_t)(row * 128 + ((kc ^ (row & 7)) << 4));
            size_t aoff = (size_t)(m0 + row) * lda + k0 + kc * 8;
            size_t boff = (size_t)(n0 + row) * ldb + k0 + kc * 8;
            CP16(sbase + doff,      AH + aoff);
            CP16(sbase + PL + doff, BH + boff);
        }
    };

    // ---- one KT stage of MMAs from ring buffer buf ----
    auto compute = [&](int buf) {
        const uint32_t bA = sb + buf * STAGEB;
        const uint32_t bB = bA + PL;
        const int t = lane >> 3, ri = lane & 7;
        #pragma unroll
        for (int kp = 0; kp < 4; kp++) {
            uint32_t af[2][4];
            #pragma unroll
            for (int ma = 0; ma < 2; ma++) {
                int row = wm + ma * 16 + (t & 1) * 8 + ri;
                int c   = 2 * kp + (t >> 1);
                uint32_t off = (uint32_t)(row * 128 + ((c ^ (row & 7)) << 4));
                ldsm4(af[ma][0], af[ma][1], af[ma][2], af[ma][3], bA + off);
            }
            #pragma unroll
            for (int np = 0; np < 4; np++) {
                int row = wn + np * 16 + (t >> 1) * 8 + ri;
                int c   = 2 * kp + (t & 1);
                uint32_t off = (uint32_t)(row * 128 + ((c ^ (row & 7)) << 4));
                uint32_t bf[4];
                ldsm4(bf[0], bf[1], bf[2], bf[3], bB + off);
                #pragma unroll
                for (int sub = 0; sub < 2; sub++) {
                    int na = np * 2 + sub;
                    #pragma unroll
                    for (int ma = 0; ma < 2; ma++)
                        mma_f16(acc[ma][na], af[ma], bf[sub * 2], bf[sub * 2 + 1]);
                }
            }
        }
    };

    // ---- software pipeline: 3-deep ring, one barrier per stage ----
    stage_load(0, 0);  CP_COMMIT();
    stage_load(KT, 1); CP_COMMIT();

    int buf = 0, nbuf = 2;
    for (int s = 0; s < nstages; s++) {
        if (s + 1 < nstages) CP_WAIT1(); else CP_WAIT0();
        __syncthreads();     // publish stage s; fences recycled buffer
        if (s + 2 < nstages) {
            // writes buffer computed at stage s-1 — all warps past it (barrier)
            stage_load((s + 2) * KT, nbuf);
            CP_COMMIT();
        }
        compute(buf);
        buf = (buf == 2) ? 0 : buf + 1;
        nbuf = (nbuf == 2) ? 0 : nbuf + 1;
    }

    // ---- epilogue ----
    #pragma unroll
    for (int ma = 0; ma < 2; ma++) {
        #pragma unroll
        for (int na = 0; na < 8; na++) {
            const int r0 = m0 + wm + ma * 16 + g;
            const int cb = n0 + wn + na * 8 + 2 * t4;
            float v[4] = {acc[ma][na][0] * scale, acc[ma][na][1] * scale,
                          acc[ma][na][2] * scale, acc[ma][na][3] * scale};
            if (outmode == 2) {
                __half* Dh = (__half*)Dp;
                #pragma unroll
                for (int hrow = 0; hrow < 2; hrow++) {
                    size_t o = (size_t)(r0 + hrow * 8) * ldd + cb;
                    __half2 p;
                    p.x = __float2half_rn(v[hrow * 2 + 0]);
                    p.y = __float2half_rn(v[hrow * 2 + 1]);
                    *(__half2*)&Dh[o] = p;
                }
            } else {
                float* D = (float*)Dp;
                #pragma unroll
                for (int hrow = 0; hrow < 2; hrow++) {
                    float* p = &D[(size_t)(r0 + hrow * 8) * ldd + cb];
                    float2 w = make_float2(v[hrow * 2], v[hrow * 2 + 1]);
                    if (outmode == 1) {
                        float2 o = *(const float2*)p;
                        w.x += o.x; w.y += o.y;
                    }
                    *(float2*)p = w;
                }
            }
        }
    }
}

// ---- single-GEMM kernel (energy, PV) ----
__global__ void __launch_bounds__(256, 2) tc_gemm(
    const __half* __restrict__ AH, const __half* __restrict__ BH,
    void* __restrict__ Dp,
    int lda, int ldb, int ldd,
    size_t strA, size_t strB, size_t strD,
    int Kdim, float scale, int outmode)
{
    extern __shared__ char smem[];
    const int bz = blockIdx.z;
    gemm_tile(AH + (size_t)bz * strA, BH + (size_t)bz * strB,
              (outmode == 2) ? (void*)((__half*)Dp + (size_t)bz * strD)
                             : (void*)((float*)Dp + (size_t)bz * strD),
              lda, ldb, ldd, Kdim, scale, outmode,
              blockIdx.y * 128, blockIdx.x * 128, smem);
}

// ---- merged 4-projection kernel: flat 320 tiles/batch ----
struct GDesc {
    const __half* A;
    const __half* B;
    void* D;
    int lda, ldb, ldd;
    size_t strA, strB, strD;
    int ntx;       // tiles along n
    int outmode;
};

__global__ void __launch_bounds__(256, 2) tc_gemm_proj(
    GDesc d0, GDesc d1, GDesc d2, GDesc d3)
{
    extern __shared__ char smem[];
    int id = blockIdx.x;
    GDesc d;
    if (id < 128)      { d = d0; }
    else if (id < 256) { d = d1; id -= 128; }
    else if (id < 288) { d = d2; id -= 256; }
    else               { d = d3; id -= 288; }
    const int bz = blockIdx.z;
    const int n0 = (id % d.ntx) * 128;
    const int m0 = (id / d.ntx) * 128;
    gemm_tile(d.A + (size_t)bz * d.strA, d.B + (size_t)bz * d.strB,
              (d.outmode == 2) ? (void*)((__half*)d.D + (size_t)bz * d.strD)
                               : (void*)((float*)d.D + (size_t)bz * d.strD),
              d.lda, d.ldb, d.ldd, CC, 1.0f, d.outmode, m0, n0, smem);
}

// ---------------------------------------------------------------------------
// Softmax over last dim (M=1024), max-free (|E| <= ~6 by construction):
// read fp16 E (pre-scaled), exp, row-sum, normalize, write fp16 P.
// ---------------------------------------------------------------------------
__global__ void __launch_bounds__(256) softmax_kernel(
    const __half* __restrict__ E, __half* __restrict__ P)
{
    const size_t rb = (size_t)blockIdx.x * MM;
    const int t = threadIdx.x;
    __half hv[4];
    *(uint2*)hv = *(const uint2*)&E[rb + t * 4];
    float e[4];
    #pragma unroll
    for (int i = 0; i < 4; i++) e[i] = __expf(__half2float(hv[i]));

    __shared__ float rsum[8];
    float s = e[0] + e[1] + e[2] + e[3];
    #pragma unroll
    for (int o = 16; o > 0; o >>= 1)
        s += __shfl_xor_sync(0xffffffffu, s, o);
    if ((t & 31) == 0) rsum[t >> 5] = s;
    __syncthreads();
    s = rsum[0];
    #pragma unroll
    for (int i = 1; i < 8; i++) s += rsum[i];

    const float inv = 1.0f / s;
    __half h[4];
    #pragma unroll
    for (int i = 0; i < 4; i++) h[i] = __float2half_rn(e[i] * inv);
    *(uint2*)&P[rb + t * 4] = *(uint2*)h;
}

// ---------------------------------------------------------------------------
// Launch
// ---------------------------------------------------------------------------
extern "C" void kernel_launch(void* const* d_in, const int* in_sizes, int n_in,
                              void* d_out, int out_size)
{
    const float* pcd_up   = (const float*)d_in[0];
    const float* pcd_down = (const float*)d_in[1];
    const float* Wq       = (const float*)d_in[2];
    const float* Wk       = (const float*)d_in[3];
    const float* Wv       = (const float*)d_in[4];
    const float* Wskip    = (const float*)d_in[5];
    float* out = (float*)d_out;

    __half *Tup, *Tdn, *Wq16, *Wk16, *Wv16, *Ws16, *Qt, *Kt, *V, *E, *P;
    cudaGetSymbolAddress((void**)&Tup, g_Tup16);
    cudaGetSymbolAddress((void**)&Tdn, g_Tdn16);
    cudaGetSymbolAddress((void**)&Wq16, g_Wq16);
    cudaGetSymbolAddress((void**)&Wk16, g_Wk16);
    cudaGetSymbolAddress((void**)&Wv16, g_Wv16);
    cudaGetSymbolAddress((void**)&Ws16, g_Ws16);
    cudaGetSymbolAddress((void**)&Qt, g_Qt16);
    cudaGetSymbolAddress((void**)&Kt, g_Kt16);
    cudaGetSymbolAddress((void**)&V, g_V16);
    cudaGetSymbolAddress((void**)&E, g_E);
    cudaGetSymbolAddress((void**)&P, g_P);

    static bool attr_done = false;
    if (!attr_done) {
        cudaFuncSetAttribute(tc_gemm,
                             cudaFuncAttributeMaxDynamicSharedMemorySize, SMEMBYTES);
        cudaFuncSetAttribute(tc_gemm_proj,
                             cudaFuncAttributeMaxDynamicSharedMemorySize, SMEMBYTES);
        attr_done = true;
    }

    const float rscale = 0.04419417382415922f;  // 1/sqrt(512)
    const size_t sNC = (size_t)NN * CC;
    const size_t sMC = (size_t)MM * CC;
    const size_t sE  = (size_t)NN * MM;

    // 0) transpose+cvt inputs; cvt weights
    transpose_cvt_kernel<<<dim3(NN / 32, CC / 32, BB), 256>>>(pcd_up, Tup, CC, NN);
    transpose_cvt_kernel<<<dim3(MM / 32, CC / 32, BB), 256>>>(pcd_down, Tdn, CC, MM);
    cvt4_kernel<<<dim3(CC * CC / 256, 4), 256>>>(
        Wq, Wk, Wv, Wskip, Wq16, Wk16, Wv16, Ws16, CC * CC);

    // 1) All four projections, one launch (320 tiles/batch):
    //    d0: Qt[n][o]  = Tup·Wq^T   (m=N, n=C, 128 tiles)
    //    d1: out[o][n] = Wskip·Tup^T (m=C, n=N, 128 tiles, fp32)
    //    d2: Kt[m][o]  = Tdn·Wk^T   (m=M, n=C, 32 tiles)
    //    d3: V[o][m]   = Wv·Tdn^T   (m=C, n=M, 32 tiles)
    GDesc d0 = {Tup,  Wq16, Qt,  CC, CC, CC, sNC, 0,   sNC, CC / 128, 2};
    GDesc d1 = {Ws16, Tup,  out, CC, CC, NN, 0,   sNC, sNC, NN / 128, 0};
    GDesc d2 = {Tdn,  Wk16, Kt,  CC, CC, CC, sMC, 0,   sMC, CC / 128, 2};
    GDesc d3 = {Wv16, Tdn,  V,   CC, CC, MM, 0,   sMC, sMC, MM / 128, 2};
    tc_gemm_proj<<<dim3(320, 1, BB), 256, SMEMBYTES>>>(d0, d1, d2, d3);

    // 2) E[n][m] = rscale * sum_c Qt[n][c] Kt[m][c] -> fp16 (scaled)
    tc_gemm<<<dim3(MM / 128, NN / 128, BB), 256, SMEMBYTES>>>(
        Qt, Kt, E, CC, CC, MM, sNC, sMC, sE, CC, rscale, 2);

    // 3) softmax over M (max-free; fp16 in/out)
    softmax_kernel<<<BB * NN, 256>>>(E, P);

    // 4) out[c][n] += sum_m V[c][m] P[n][m]
    tc_gemm<<<dim3(NN / 128, CC / 128, BB), 256, SMEMBYTES>>>(
        V, P, out, MM, MM, NN, sMC, sE, sNC, MM, 1.0f, 1);
}

// round 11
// speedup vs baseline: 2.6217x; 1.0297x over previous
#include <cuda_runtime.h>
#include <cuda_fp16.h>
#include <cstdint>
#include <math.h>

// Problem constants
#define BB 8
#define CC 512
#define NN 4096
#define MM 1024

// ---------------------------------------------------------------------------
// Scratch (no cudaMalloc): fp16 operand planes; fp16 energy / attention.
// ---------------------------------------------------------------------------
__device__ __half g_Tup16[(size_t)BB * NN * CC];  // pcd_up^T  [B][N][C]
__device__ __half g_Tdn16[(size_t)BB * MM * CC];  // pcd_down^T [B][M][C]
__device__ __half g_Wq16[CC * CC], g_Wk16[CC * CC];
__device__ __half g_Wv16[CC * CC], g_Ws16[CC * CC];
__device__ __half g_Qt16[(size_t)BB * NN * CC];   // Q^T [B][N][C]
__device__ __half g_Kt16[(size_t)BB * MM * CC];   // K^T [B][M][C]
__device__ __half g_V16 [(size_t)BB * CC * MM];   // V [B][C][M]
__device__ __half g_E   [(size_t)BB * NN * MM];   // energy fp16 (scaled)
__device__ __half g_P   [(size_t)BB * NN * MM];   // attention fp16

// ---------------------------------------------------------------------------
// helpers
// ---------------------------------------------------------------------------
__device__ __forceinline__ uint32_t smem_u32(const void* p) {
    uint32_t a;
    asm("{ .reg .u64 t; cvta.to.shared.u64 t, %1; cvt.u32.u64 %0, t; }"
        : "=r"(a) : "l"(p));
    return a;
}

__device__ __forceinline__ void mma_f16(float* c, const uint32_t* a,
                                        uint32_t b0, uint32_t b1) {
    asm volatile(
        "mma.sync.aligned.m16n8k16.row.col.f32.f16.f16.f32 "
        "{%0,%1,%2,%3}, {%4,%5,%6,%7}, {%8,%9}, {%0,%1,%2,%3};"
        : "+f"(c[0]), "+f"(c[1]), "+f"(c[2]), "+f"(c[3])
        : "r"(a[0]), "r"(a[1]), "r"(a[2]), "r"(a[3]), "r"(b0), "r"(b1));
}

__device__ __forceinline__ void ldsm4(uint32_t& r0, uint32_t& r1,
                                      uint32_t& r2, uint32_t& r3, uint32_t addr) {
    asm volatile("ldmatrix.sync.aligned.m8n8.x4.shared.b16 {%0,%1,%2,%3}, [%4];"
                 : "=r"(r0), "=r"(r1), "=r"(r2), "=r"(r3) : "r"(addr));
}

#define CP16(dst, src) \
    asm volatile("cp.async.cg.shared.global [%0], [%1], 16;" :: "r"(dst), "l"(src))
#define CP_COMMIT() asm volatile("cp.async.commit_group;" ::: "memory")
#define CP_WAIT1()  asm volatile("cp.async.wait_group 1;" ::: "memory")
#define CP_WAIT0()  asm volatile("cp.async.wait_group 0;" ::: "memory")

// ---------------------------------------------------------------------------
// transpose + convert: fp32 [rows, cols] per batch -> fp16 [cols, rows]
// ---------------------------------------------------------------------------
__global__ void __launch_bounds__(256) transpose_cvt_kernel(
    const float* __restrict__ in, __half* __restrict__ oh, int rows, int cols)
{
    __shared__ float t[32][33];
    const int b = blockIdx.z;
    in += (size_t)b * rows * cols;
    oh += (size_t)b * rows * cols;
    const int r0 = blockIdx.y * 32, c0 = blockIdx.x * 32;
    const int tx = threadIdx.x & 31, ty = threadIdx.x >> 5;
    #pragma unroll
    for (int i = 0; i < 32; i += 8)
        t[ty + i][tx] = in[(size_t)(r0 + ty + i) * cols + c0 + tx];
    __syncthreads();
    #pragma unroll
    for (int i = 0; i < 32; i += 8)
        oh[(size_t)(c0 + ty + i) * rows + r0 + tx] = __float2half_rn(t[tx][ty + i]);
}

// one kernel converts all four weight matrices (blockIdx.y selects)
__global__ void __launch_bounds__(256) cvt4_kernel(
    const float* __restrict__ W0, const float* __restrict__ W1,
    const float* __restrict__ W2, const float* __restrict__ W3,
    __half* __restrict__ H0, __half* __restrict__ H1,
    __half* __restrict__ H2, __half* __restrict__ H3, int n)
{
    int i = blockIdx.x * 256 + threadIdx.x;
    if (i >= n) return;
    const float* W;
    __half* H;
    switch (blockIdx.y) {
        case 0:  W = W0; H = H0; break;
        case 1:  W = W1; H = H1; break;
        case 2:  W = W2; H = H2; break;
        default: W = W3; H = H3; break;
    }
    H[i] = __float2half_rn(W[i]);
}

// ---------------------------------------------------------------------------
// Two-phase GEMM tile body (phase 2 optional):
//   D[m, n] (CTA tile 128x128) = scale * ( sum_{k<K1} A1[m][k] B1[n][k]
//                                        + sum_{k<K2} A2[m][k] B2[n][k] )
// outmode: 0 = fp32 store, 2 = fp16 store.
// KT=64; 3-stage cp.async ring (96 KB); one __syncthreads per stage.
// Rows of 128 B, 8-chunk XOR swizzle: phys16B = kc ^ (row & 7).
// 8 warps of 32x64.
// ---------------------------------------------------------------------------
#define KT 64
#define PL 16384                   // 128 rows x 128 B plane
#define STAGEB (2 * PL)            // 32 KB
#define SMEMBYTES (3 * STAGEB)     // 96 KB

__device__ __forceinline__ void gemm_tile2(
    const __half* __restrict__ A1, const __half* __restrict__ B1,
    int lda1, int ldb1, int K1,
    const __half* __restrict__ A2, const __half* __restrict__ B2,
    int lda2, int ldb2, int K2,
    void* __restrict__ Dp, int ldd,
    float scale, int outmode,
    int m0, int n0, char* smem)
{
    const uint32_t sb = smem_u32(smem);
    const int tid  = threadIdx.x;
    const int wid  = tid >> 5;
    const int lane = tid & 31;
    const int g    = lane >> 2;
    const int t4   = lane & 3;
    const int wm   = (wid >> 1) * 32;   // 4 warps along m (128)
    const int wn   = (wid & 1) * 64;    // 2 warps along n (128)

    float acc[2][8][4] = {};
    const int ns1 = K1 / KT;
    const int nstages = ns1 + K2 / KT;

    // ---- cp.async one KT stage (global stage index s) into buffer buf ----
    auto stage_load = [&](int s, int buf) {
        const __half* A;
        const __half* B;
        int la, lb, k0;
        if (s < ns1) { A = A1; B = B1; la = lda1; lb = ldb1; k0 = s * KT; }
        else         { A = A2; B = B2; la = lda2; lb = ldb2; k0 = (s - ns1) * KT; }
        const uint32_t sbase = sb + buf * STAGEB;
        #pragma unroll
        for (int i = 0; i < 4; i++) {
            int f = tid + i * 256;          // 0..1023
            int row = f >> 3, kc = f & 7;
            uint32_t doff = (uint32_t)(row * 128 + ((kc ^ (row & 7)) << 4));
            size_t aoff = (size_t)(m0 + row) * la + k0 + kc * 8;
            size_t boff = (size_t)(n0 + row) * lb + k0 + kc * 8;
            CP16(sbase + doff,      A + aoff);
            CP16(sbase + PL + doff, B + boff);
        }
    };

    // ---- one KT stage of MMAs from ring buffer buf ----
    auto compute = [&](int buf) {
        const uint32_t bA = sb + buf * STAGEB;
        const uint32_t bB = bA + PL;
        const int t = lane >> 3, ri = lane & 7;
        #pragma unroll
        for (int kp = 0; kp < 4; kp++) {
            uint32_t af[2][4];
            #pragma unroll
            for (int ma = 0; ma < 2; ma++) {
                int row = wm + ma * 16 + (t & 1) * 8 + ri;
                int c   = 2 * kp + (t >> 1);
                uint32_t off = (uint32_t)(row * 128 + ((c ^ (row & 7)) << 4));
                ldsm4(af[ma][0], af[ma][1], af[ma][2], af[ma][3], bA + off);
            }
            #pragma unroll
            for (int np = 0; np < 4; np++) {
                int row = wn + np * 16 + (t >> 1) * 8 + ri;
                int c   = 2 * kp + (t & 1);
                uint32_t off = (uint32_t)(row * 128 + ((c ^ (row & 7)) << 4));
                uint32_t bf[4];
                ldsm4(bf[0], bf[1], bf[2], bf[3], bB + off);
                #pragma unroll
                for (int sub = 0; sub < 2; sub++) {
                    int na = np * 2 + sub;
                    #pragma unroll
                    for (int ma = 0; ma < 2; ma++)
                        mma_f16(acc[ma][na], af[ma], bf[sub * 2], bf[sub * 2 + 1]);
                }
            }
        }
    };

    // ---- software pipeline: 3-deep ring, one barrier per stage ----
    stage_load(0, 0); CP_COMMIT();
    stage_load(1, 1); CP_COMMIT();

    int buf = 0, nbuf = 2;
    for (int s = 0; s < nstages; s++) {
        if (s + 1 < nstages) CP_WAIT1(); else CP_WAIT0();
        __syncthreads();     // publish stage s; fences recycled buffer
        if (s + 2 < nstages) {
            // writes buffer computed at stage s-1 — all warps past it (barrier)
            stage_load(s + 2, nbuf);
            CP_COMMIT();
        }
        compute(buf);
        buf = (buf == 2) ? 0 : buf + 1;
        nbuf = (nbuf == 2) ? 0 : nbuf + 1;
    }

    // ---- epilogue: single store (no RMW) ----
    #pragma unroll
    for (int ma = 0; ma < 2; ma++) {
        #pragma unroll
        for (int na = 0; na < 8; na++) {
            const int r0 = m0 + wm + ma * 16 + g;
            const int cb = n0 + wn + na * 8 + 2 * t4;
            float v[4] = {acc[ma][na][0] * scale, acc[ma][na][1] * scale,
                          acc[ma][na][2] * scale, acc[ma][na][3] * scale};
            if (outmode == 2) {
                __half* Dh = (__half*)Dp;
                #pragma unroll
                for (int hrow = 0; hrow < 2; hrow++) {
                    size_t o = (size_t)(r0 + hrow * 8) * ldd + cb;
                    __half2 p;
                    p.x = __float2half_rn(v[hrow * 2 + 0]);
                    p.y = __float2half_rn(v[hrow * 2 + 1]);
                    *(__half2*)&Dh[o] = p;
                }
            } else {
                float* D = (float*)Dp;
                #pragma unroll
                for (int hrow = 0; hrow < 2; hrow++)
                    *(float2*)&D[(size_t)(r0 + hrow * 8) * ldd + cb] =
                        make_float2(v[hrow * 2], v[hrow * 2 + 1]);
            }
        }
    }
}

// ---- single-GEMM kernel (energy) ----
__global__ void __launch_bounds__(256, 2) tc_gemm(
    const __half* __restrict__ AH, const __half* __restrict__ BH,
    void* __restrict__ Dp,
    int lda, int ldb, int ldd,
    size_t strA, size_t strB, size_t strD,
    int Kdim, float scale, int outmode)
{
    extern __shared__ char smem[];
    const int bz = blockIdx.z;
    gemm_tile2(AH + (size_t)bz * strA, BH + (size_t)bz * strB,
               lda, ldb, Kdim, nullptr, nullptr, 0, 0, 0,
               (outmode == 2) ? (void*)((__half*)Dp + (size_t)bz * strD)
                              : (void*)((float*)Dp + (size_t)bz * strD),
               ldd, scale, outmode, blockIdx.y * 128, blockIdx.x * 128, smem);
}

// ---- fused skip + PV kernel: out[c][n] = Wskip·Tup^T + V·P^T, one write ----
__global__ void __launch_bounds__(256, 2) tc_gemm_skip_pv(
    const __half* __restrict__ Ws, const __half* __restrict__ Tup,
    const __half* __restrict__ V,  const __half* __restrict__ P,
    float* __restrict__ out)
{
    extern __shared__ char smem[];
    const int bz = blockIdx.z;
    gemm_tile2(Ws, Tup + (size_t)bz * NN * CC, CC, CC, CC,
               V + (size_t)bz * CC * MM, P + (size_t)bz * NN * MM, MM, MM, MM,
               out + (size_t)bz * CC * NN, NN, 1.0f, 0,
               blockIdx.y * 128, blockIdx.x * 128, smem);
}

// ---- merged 3-projection kernel (Qt, Kt, V): flat 192 tiles/batch ----
struct GDesc {
    const __half* A;
    const __half* B;
    void* D;
    int lda, ldb, ldd;
    size_t strA, strB, strD;
    int ntx;       // tiles along n
    int outmode;
};

__global__ void __launch_bounds__(256, 2) tc_gemm_proj(
    GDesc d0, GDesc d1, GDesc d2)
{
    extern __shared__ char smem[];
    int id = blockIdx.x;
    GDesc d;
    if (id < 128)      { d = d0; }
    else if (id < 160) { d = d1; id -= 128; }
    else               { d = d2; id -= 160; }
    const int bz = blockIdx.z;
    const int n0 = (id % d.ntx) * 128;
    const int m0 = (id / d.ntx) * 128;
    gemm_tile2(d.A + (size_t)bz * d.strA, d.B + (size_t)bz * d.strB,
               d.lda, d.ldb, CC, nullptr, nullptr, 0, 0, 0,
               (d.outmode == 2) ? (void*)((__half*)d.D + (size_t)bz * d.strD)
                                : (void*)((float*)d.D + (size_t)bz * d.strD),
               d.ldd, 1.0f, d.outmode, m0, n0, smem);
}

// ---------------------------------------------------------------------------
// Softmax over last dim (M=1024), max-free (|E| <= ~6 by construction):
// read fp16 E (pre-scaled), exp, row-sum, normalize, write fp16 P.
// ---------------------------------------------------------------------------
__global__ void __launch_bounds__(256) softmax_kernel(
    const __half* __restrict__ E, __half* __restrict__ P)
{
    const size_t rb = (size_t)blockIdx.x * MM;
    const int t = threadIdx.x;
    __half hv[4];
    *(uint2*)hv = *(const uint2*)&E[rb + t * 4];
    float e[4];
    #pragma unroll
    for (int i = 0; i < 4; i++) e[i] = __expf(__half2float(hv[i]));

    __shared__ float rsum[8];
    float s = e[0] + e[1] + e[2] + e[3];
    #pragma unroll
    for (int o = 16; o > 0; o >>= 1)
        s += __shfl_xor_sync(0xffffffffu, s, o);
    if ((t & 31) == 0) rsum[t >> 5] = s;
    __syncthreads();
    s = rsum[0];
    #pragma unroll
    for (int i = 1; i < 8; i++) s += rsum[i];

    const float inv = 1.0f / s;
    __half h[4];
    #pragma unroll
    for (int i = 0; i < 4; i++) h[i] = __float2half_rn(e[i] * inv);
    *(uint2*)&P[rb + t * 4] = *(uint2*)h;
}

// ---------------------------------------------------------------------------
// Launch
// ---------------------------------------------------------------------------
extern "C" void kernel_launch(void* const* d_in, const int* in_sizes, int n_in,
                              void* d_out, int out_size)
{
    const float* pcd_up   = (const float*)d_in[0];
    const float* pcd_down = (const float*)d_in[1];
    const float* Wq       = (const float*)d_in[2];
    const float* Wk       = (const float*)d_in[3];
    const float* Wv       = (const float*)d_in[4];
    const float* Wskip    = (const float*)d_in[5];
    float* out = (float*)d_out;

    __half *Tup, *Tdn, *Wq16, *Wk16, *Wv16, *Ws16, *Qt, *Kt, *V, *E, *P;
    cudaGetSymbolAddress((void**)&Tup, g_Tup16);
    cudaGetSymbolAddress((void**)&Tdn, g_Tdn16);
    cudaGetSymbolAddress((void**)&Wq16, g_Wq16);
    cudaGetSymbolAddress((void**)&Wk16, g_Wk16);
    cudaGetSymbolAddress((void**)&Wv16, g_Wv16);
    cudaGetSymbolAddress((void**)&Ws16, g_Ws16);
    cudaGetSymbolAddress((void**)&Qt, g_Qt16);
    cudaGetSymbolAddress((void**)&Kt, g_Kt16);
    cudaGetSymbolAddress((void**)&V, g_V16);
    cudaGetSymbolAddress((void**)&E, g_E);
    cudaGetSymbolAddress((void**)&P, g_P);

    static bool attr_done = false;
    if (!attr_done) {
        cudaFuncSetAttribute(tc_gemm,
                             cudaFuncAttributeMaxDynamicSharedMemorySize, SMEMBYTES);
        cudaFuncSetAttribute(tc_gemm_proj,
                             cudaFuncAttributeMaxDynamicSharedMemorySize, SMEMBYTES);
        cudaFuncSetAttribute(tc_gemm_skip_pv,
                             cudaFuncAttributeMaxDynamicSharedMemorySize, SMEMBYTES);
        attr_done = true;
    }

    const float rscale = 0.04419417382415922f;  // 1/sqrt(512)
    const size_t sNC = (size_t)NN * CC;
    const size_t sMC = (size_t)MM * CC;
    const size_t sE  = (size_t)NN * MM;

    // 0) transpose+cvt inputs; cvt weights
    transpose_cvt_kernel<<<dim3(NN / 32, CC / 32, BB), 256>>>(pcd_up, Tup, CC, NN);
    transpose_cvt_kernel<<<dim3(MM / 32, CC / 32, BB), 256>>>(pcd_down, Tdn, CC, MM);
    cvt4_kernel<<<dim3(CC * CC / 256, 4), 256>>>(
        Wq, Wk, Wv, Wskip, Wq16, Wk16, Wv16, Ws16, CC * CC);

    // 1) Qt/Kt/V projections, one launch (192 tiles/batch):
    //    d0: Qt[n][o] = Tup·Wq^T  (m=N, n=C, 128 tiles)
    //    d1: Kt[m][o] = Tdn·Wk^T  (m=M, n=C, 32 tiles)
    //    d2: V[o][m]  = Wv·Tdn^T  (m=C, n=M, 32 tiles)
    GDesc d0 = {Tup,  Wq16, Qt, CC, CC, CC, sNC, 0,   sNC, CC / 128, 2};
    GDesc d1 = {Tdn,  Wk16, Kt, CC, CC, CC, sMC, 0,   sMC, CC / 128, 2};
    GDesc d2 = {Wv16, Tdn,  V,  CC, CC, MM, 0,   sMC, sMC, MM / 128, 2};
    tc_gemm_proj<<<dim3(192, 1, BB), 256, SMEMBYTES>>>(d0, d1, d2);

    // 2) E[n][m] = rscale * sum_c Qt[n][c] Kt[m][c] -> fp16 (scaled)
    tc_gemm<<<dim3(MM / 128, NN / 128, BB), 256, SMEMBYTES>>>(
        Qt, Kt, E, CC, CC, MM, sNC, sMC, sE, CC, rscale, 2);

    // 3) softmax over M (max-free; fp16 in/out)
    softmax_kernel<<<BB * NN, 256>>>(E, P);

    // 4) out[c][n] = Wskip·Tup^T + V·P^T  (fused, single fp32 write)
    tc_gemm_skip_pv<<<dim3(NN / 128, CC / 128, BB), 256, SMEMBYTES>>>(
        Ws16, Tup, V, P, out);
}

// round 12
// speedup vs baseline: 2.8204x; 1.0758x over previous
#include <cuda_runtime.h>
#include <cuda_fp16.h>
#include <cstdint>
#include <math.h>

// Problem constants
#define BB 8
#define CC 512
#define NN 4096
#define MM 1024

// ---------------------------------------------------------------------------
// Scratch (no cudaMalloc): fp16 operand planes; fp16 expE; fp32 row sums.
// ---------------------------------------------------------------------------
__device__ __half g_Tup16[(size_t)BB * NN * CC];  // pcd_up^T  [B][N][C]
__device__ __half g_Tdn16[(size_t)BB * MM * CC];  // pcd_down^T [B][M][C]
__device__ __half g_Wq16[CC * CC], g_Wk16[CC * CC];
__device__ __half g_Wv16[CC * CC], g_Ws16[CC * CC];
__device__ __half g_Qt16[(size_t)BB * NN * CC];   // Q^T [B][N][C]
__device__ __half g_Kt16[(size_t)BB * MM * CC];   // K^T [B][M][C]
__device__ __half g_V16 [(size_t)BB * CC * MM];   // V [B][C][M]
__device__ __half g_P   [(size_t)BB * NN * MM];   // expE (unnormalized attn)
__device__ float  g_RS  [(size_t)BB * NN];        // row sums of expE

// ---------------------------------------------------------------------------
// helpers
// ---------------------------------------------------------------------------
__device__ __forceinline__ uint32_t smem_u32(const void* p) {
    uint32_t a;
    asm("{ .reg .u64 t; cvta.to.shared.u64 t, %1; cvt.u32.u64 %0, t; }"
        : "=r"(a) : "l"(p));
    return a;
}

__device__ __forceinline__ void mma_f16(float* c, const uint32_t* a,
                                        uint32_t b0, uint32_t b1) {
    asm volatile(
        "mma.sync.aligned.m16n8k16.row.col.f32.f16.f16.f32 "
        "{%0,%1,%2,%3}, {%4,%5,%6,%7}, {%8,%9}, {%0,%1,%2,%3};"
        : "+f"(c[0]), "+f"(c[1]), "+f"(c[2]), "+f"(c[3])
        : "r"(a[0]), "r"(a[1]), "r"(a[2]), "r"(a[3]), "r"(b0), "r"(b1));
}

__device__ __forceinline__ void ldsm4(uint32_t& r0, uint32_t& r1,
                                      uint32_t& r2, uint32_t& r3, uint32_t addr) {
    asm volatile("ldmatrix.sync.aligned.m8n8.x4.shared.b16 {%0,%1,%2,%3}, [%4];"
                 : "=r"(r0), "=r"(r1), "=r"(r2), "=r"(r3) : "r"(addr));
}

#define CP16(dst, src) \
    asm volatile("cp.async.cg.shared.global [%0], [%1], 16;" :: "r"(dst), "l"(src))
#define CP_COMMIT() asm volatile("cp.async.commit_group;" ::: "memory")
#define CP_WAIT1()  asm volatile("cp.async.wait_group 1;" ::: "memory")
#define CP_WAIT0()  asm volatile("cp.async.wait_group 0;" ::: "memory")

// ---------------------------------------------------------------------------
// merged transpose + convert for both inputs:
//   pcd_up  fp32 [C, N] -> Tup fp16 [N, C]
//   pcd_down fp32 [C, M] -> Tdn fp16 [M, C]
// ---------------------------------------------------------------------------
#define UP_TILES ((NN / 32) * (CC / 32))
#define DN_TILES ((MM / 32) * (CC / 32))

__global__ void __launch_bounds__(256) transpose_cvt2_kernel(
    const float* __restrict__ up, const float* __restrict__ dn,
    __half* __restrict__ tup, __half* __restrict__ tdn)
{
    __shared__ float t[32][33];
    int bx = blockIdx.x;
    const float* in;
    __half* oh;
    int cols;
    if (bx < UP_TILES) { in = up; oh = tup; cols = NN; }
    else               { bx -= UP_TILES; in = dn; oh = tdn; cols = MM; }
    const int b = blockIdx.z;
    in += (size_t)b * CC * cols;
    oh += (size_t)b * CC * cols;
    const int xt = cols / 32;
    const int c0 = (bx % xt) * 32, r0 = (bx / xt) * 32;
    const int tx = threadIdx.x & 31, ty = threadIdx.x >> 5;
    #pragma unroll
    for (int i = 0; i < 32; i += 8)
        t[ty + i][tx] = in[(size_t)(r0 + ty + i) * cols + c0 + tx];
    __syncthreads();
    #pragma unroll
    for (int i = 0; i < 32; i += 8)
        oh[(size_t)(c0 + ty + i) * CC + r0 + tx] = __float2half_rn(t[tx][ty + i]);
}

// cvt all four weight matrices + zero row sums (blockIdx.y selects)
__global__ void __launch_bounds__(256) cvt4_kernel(
    const float* __restrict__ W0, const float* __restrict__ W1,
    const float* __restrict__ W2, const float* __restrict__ W3,
    __half* __restrict__ H0, __half* __restrict__ H1,
    __half* __restrict__ H2, __half* __restrict__ H3,
    float* __restrict__ RS, int n)
{
    int i = blockIdx.x * 256 + threadIdx.x;
    if (blockIdx.y == 4) {                 // zero row sums (BB*NN floats)
        if (i < BB * NN) RS[i] = 0.0f;
        return;
    }
    if (i >= n) return;
    const float* W;
    __half* H;
    switch (blockIdx.y) {
        case 0:  W = W0; H = H0; break;
        case 1:  W = W1; H = H1; break;
        case 2:  W = W2; H = H2; break;
        default: W = W3; H = H3; break;
    }
    H[i] = __float2half_rn(W[i]);
}

// ---------------------------------------------------------------------------
// Two-phase GEMM tile body.
//   acc = sum_{k<K1} A1[m][k] B1[n][k]  (phase 1)
//   [optional: acc[:,n] /= divrs[n] at phase boundary]
//   acc += sum_{k<K2} A2[m][k] B2[n][k] (phase 2)
// outmode: 0 = fp32 store, 2 = fp16 store,
//          3 = expE epilogue: store fp16 exp(acc*scale), atomicAdd row sums
//              of exp into rs[row].
// KT=64; 3-stage cp.async ring (96 KB); one __syncthreads per stage.
// Rows of 128 B, 8-chunk XOR swizzle: phys16B = kc ^ (row & 7).
// 8 warps of 32x64.
// ---------------------------------------------------------------------------
#define KT 64
#define PL 16384                   // 128 rows x 128 B plane
#define STAGEB (2 * PL)            // 32 KB
#define SMEMBYTES (3 * STAGEB)     // 96 KB

__device__ __forceinline__ void gemm_tile2(
    const __half* __restrict__ A1, const __half* __restrict__ B1,
    int lda1, int ldb1, int K1,
    const __half* __restrict__ A2, const __half* __restrict__ B2,
    int lda2, int ldb2, int K2,
    void* __restrict__ Dp, int ldd,
    float scale, int outmode,
    int m0, int n0, char* smem,
    float* __restrict__ rs,            // outmode 3: atomic row-sum base
    const float* __restrict__ divrs)   // phase-boundary divisor (or null)
{
    const uint32_t sb = smem_u32(smem);
    const int tid  = threadIdx.x;
    const int wid  = tid >> 5;
    const int lane = tid & 31;
    const int g    = lane >> 2;
    const int t4   = lane & 3;
    const int wm   = (wid >> 1) * 32;   // 4 warps along m (128)
    const int wn   = (wid & 1) * 64;    // 2 warps along n (128)

    float acc[2][8][4] = {};
    const int ns1 = K1 / KT;
    const int nstages = ns1 + K2 / KT;

    // ---- cp.async one KT stage (global stage index s) into buffer buf ----
    auto stage_load = [&](int s, int buf) {
        const __half* A;
        const __half* B;
        int la, lb, k0;
        if (s < ns1) { A = A1; B = B1; la = lda1; lb = ldb1; k0 = s * KT; }
        else         { A = A2; B = B2; la = lda2; lb = ldb2; k0 = (s - ns1) * KT; }
        const uint32_t sbase = sb + buf * STAGEB;
        #pragma unroll
        for (int i = 0; i < 4; i++) {
            int f = tid + i * 256;          // 0..1023
            int row = f >> 3, kc = f & 7;
            uint32_t doff = (uint32_t)(row * 128 + ((kc ^ (row & 7)) << 4));
            size_t aoff = (size_t)(m0 + row) * la + k0 + kc * 8;
            size_t boff = (size_t)(n0 + row) * lb + k0 + kc * 8;
            CP16(sbase + doff,      A + aoff);
            CP16(sbase + PL + doff, B + boff);
        }
    };

    // ---- one KT stage of MMAs from ring buffer buf ----
    auto compute = [&](int buf) {
        const uint32_t bA = sb + buf * STAGEB;
        const uint32_t bB = bA + PL;
        const int t = lane >> 3, ri = lane & 7;
        #pragma unroll
        for (int kp = 0; kp < 4; kp++) {
            uint32_t af[2][4];
            #pragma unroll
            for (int ma = 0; ma < 2; ma++) {
                int row = wm + ma * 16 + (t & 1) * 8 + ri;
                int c   = 2 * kp + (t >> 1);
                uint32_t off = (uint32_t)(row * 128 + ((c ^ (row & 7)) << 4));
                ldsm4(af[ma][0], af[ma][1], af[ma][2], af[ma][3], bA + off);
            }
            #pragma unroll
            for (int np = 0; np < 4; np++) {
                int row = wn + np * 16 + (t >> 1) * 8 + ri;
                int c   = 2 * kp + (t & 1);
                uint32_t off = (uint32_t)(row * 128 + ((c ^ (row & 7)) << 4));
                uint32_t bf[4];
                ldsm4(bf[0], bf[1], bf[2], bf[3], bB + off);
                #pragma unroll
                for (int sub = 0; sub < 2; sub++) {
                    int na = np * 2 + sub;
                    #pragma unroll
                    for (int ma = 0; ma < 2; ma++)
                        mma_f16(acc[ma][na], af[ma], bf[sub * 2], bf[sub * 2 + 1]);
                }
            }
        }
    };

    // ---- software pipeline: 3-deep ring, one barrier per stage ----
    stage_load(0, 0); CP_COMMIT();
    stage_load(1, 1); CP_COMMIT();

    int buf = 0, nbuf = 2;
    for (int s = 0; s < nstages; s++) {
        if (s + 1 < nstages) CP_WAIT1(); else CP_WAIT0();
        __syncthreads();     // publish stage s; fences recycled buffer
        if (s + 2 < nstages) {
            stage_load(s + 2, nbuf);
            CP_COMMIT();
        }
        compute(buf);
        buf = (buf == 2) ? 0 : buf + 1;
        nbuf = (nbuf == 2) ? 0 : nbuf + 1;

        // phase boundary: normalize phase-1 accumulator per output column
        if (divrs && s == ns1 - 1) {
            #pragma unroll
            for (int na = 0; na < 8; na++) {
                const int cb = n0 + wn + na * 8 + 2 * t4;
                float i0 = 1.0f / divrs[cb];
                float i1 = 1.0f / divrs[cb + 1];
                #pragma unroll
                for (int ma = 0; ma < 2; ma++) {
                    acc[ma][na][0] *= i0;
                    acc[ma][na][1] *= i1;
                    acc[ma][na][2] *= i0;
                    acc[ma][na][3] *= i1;
                }
            }
        }
    }

    // ---- epilogue ----
    if (outmode == 3) {
        __half* Dh = (__half*)Dp;
        float rp[2][2] = {{0.f, 0.f}, {0.f, 0.f}};
        #pragma unroll
        for (int ma = 0; ma < 2; ma++) {
            #pragma unroll
            for (int na = 0; na < 8; na++) {
                const int r0 = m0 + wm + ma * 16 + g;
                const int cb = n0 + wn + na * 8 + 2 * t4;
                float v0 = __expf(acc[ma][na][0] * scale);
                float v1 = __expf(acc[ma][na][1] * scale);
                float v2 = __expf(acc[ma][na][2] * scale);
                float v3 = __expf(acc[ma][na][3] * scale);
                __half2 p0; p0.x = __float2half_rn(v0); p0.y = __float2half_rn(v1);
                __half2 p1; p1.x = __float2half_rn(v2); p1.y = __float2half_rn(v3);
                *(__half2*)&Dh[(size_t)r0 * ldd + cb] = p0;
                *(__half2*)&Dh[(size_t)(r0 + 8) * ldd + cb] = p1;
                rp[ma][0] += v0 + v1;
                rp[ma][1] += v2 + v3;
            }
        }
        // reduce partial row sums across the 4 t4-lanes sharing each row
        #pragma unroll
        for (int o = 1; o < 4; o <<= 1) {
            rp[0][0] += __shfl_xor_sync(0xffffffffu, rp[0][0], o);
            rp[0][1] += __shfl_xor_sync(0xffffffffu, rp[0][1], o);
            rp[1][0] += __shfl_xor_sync(0xffffffffu, rp[1][0], o);
            rp[1][1] += __shfl_xor_sync(0xffffffffu, rp[1][1], o);
        }
        if (t4 == 0) {
            #pragma unroll
            for (int ma = 0; ma < 2; ma++)
                #pragma unroll
                for (int h = 0; h < 2; h++)
                    atomicAdd(&rs[m0 + wm + ma * 16 + g + h * 8], rp[ma][h]);
        }
        return;
    }

    #pragma unroll
    for (int ma = 0; ma < 2; ma++) {
        #pragma unroll
        for (int na = 0; na < 8; na++) {
            const int r0 = m0 + wm + ma * 16 + g;
            const int cb = n0 + wn + na * 8 + 2 * t4;
            float v[4] = {acc[ma][na][0] * scale, acc[ma][na][1] * scale,
                          acc[ma][na][2] * scale, acc[ma][na][3] * scale};
            if (outmode == 2) {
                __half* Dh = (__half*)Dp;
                #pragma unroll
                for (int hrow = 0; hrow < 2; hrow++) {
                    size_t o = (size_t)(r0 + hrow * 8) * ldd + cb;
                    __half2 p;
                    p.x = __float2half_rn(v[hrow * 2 + 0]);
                    p.y = __float2half_rn(v[hrow * 2 + 1]);
                    *(__half2*)&Dh[o] = p;
                }
            } else {
                float* D = (float*)Dp;
                #pragma unroll
                for (int hrow = 0; hrow < 2; hrow++)
                    *(float2*)&D[(size_t)(r0 + hrow * 8) * ldd + cb] =
                        make_float2(v[hrow * 2], v[hrow * 2 + 1]);
            }
        }
    }
}

// ---- energy kernel: expE + row sums ----
__global__ void __launch_bounds__(256, 2) tc_gemm_energy(
    const __half* __restrict__ Qt, const __half* __restrict__ Kt,
    __half* __restrict__ P, float* __restrict__ RS, float scale)
{
    extern __shared__ char smem[];
    const int bz = blockIdx.z;
    gemm_tile2(Qt + (size_t)bz * NN * CC, Kt + (size_t)bz * MM * CC,
               CC, CC, CC, nullptr, nullptr, 0, 0, 0,
               P + (size_t)bz * NN * MM, MM, scale, 3,
               blockIdx.y * 128, blockIdx.x * 128, smem,
               RS + (size_t)bz * NN, nullptr);
}

// ---- fused PV + skip kernel: out = (V·P^T)/rowsum + Wskip·Tup^T ----
__global__ void __launch_bounds__(256, 2) tc_gemm_pv_skip(
    const __half* __restrict__ V,  const __half* __restrict__ P,
    const __half* __restrict__ Ws, const __half* __restrict__ Tup,
    const float* __restrict__ RS, float* __restrict__ out)
{
    extern __shared__ char smem[];
    const int bz = blockIdx.z;
    gemm_tile2(V + (size_t)bz * CC * MM, P + (size_t)bz * NN * MM,
               MM, MM, MM,
               Ws, Tup + (size_t)bz * NN * CC, CC, CC, CC,
               out + (size_t)bz * CC * NN, NN, 1.0f, 0,
               blockIdx.y * 128, blockIdx.x * 128, smem,
               nullptr, RS + (size_t)bz * NN);
}

// ---- merged 3-projection kernel (Qt, Kt, V): flat 192 tiles/batch ----
struct GDesc {
    const __half* A;
    const __half* B;
    void* D;
    int lda, ldb, ldd;
    size_t strA, strB, strD;
    int ntx;       // tiles along n
    int outmode;
};

__global__ void __launch_bounds__(256, 2) tc_gemm_proj(
    GDesc d0, GDesc d1, GDesc d2)
{
    extern __shared__ char smem[];
    int id = blockIdx.x;
    GDesc d;
    if (id < 128)      { d = d0; }
    else if (id < 160) { d = d1; id -= 128; }
    else               { d = d2; id -= 160; }
    const int bz = blockIdx.z;
    const int n0 = (id % d.ntx) * 128;
    const int m0 = (id / d.ntx) * 128;
    gemm_tile2(d.A + (size_t)bz * d.strA, d.B + (size_t)bz * d.strB,
               d.lda, d.ldb, CC, nullptr, nullptr, 0, 0, 0,
               (d.outmode == 2) ? (void*)((__half*)d.D + (size_t)bz * d.strD)
                                : (void*)((float*)d.D + (size_t)bz * d.strD),
               d.ldd, 1.0f, d.outmode, m0, n0, smem, nullptr, nullptr);
}

// ---------------------------------------------------------------------------
// Launch
// ---------------------------------------------------------------------------
extern "C" void kernel_launch(void* const* d_in, const int* in_sizes, int n_in,
                              void* d_out, int out_size)
{
    const float* pcd_up   = (const float*)d_in[0];
    const float* pcd_down = (const float*)d_in[1];
    const float* Wq       = (const float*)d_in[2];
    const float* Wk       = (const float*)d_in[3];
    const float* Wv       = (const float*)d_in[4];
    const float* Wskip    = (const float*)d_in[5];
    float* out = (float*)d_out;

    __half *Tup, *Tdn, *Wq16, *Wk16, *Wv16, *Ws16, *Qt, *Kt, *V, *P;
    float *RS;
    cudaGetSymbolAddress((void**)&Tup, g_Tup16);
    cudaGetSymbolAddress((void**)&Tdn, g_Tdn16);
    cudaGetSymbolAddress((void**)&Wq16, g_Wq16);
    cudaGetSymbolAddress((void**)&Wk16, g_Wk16);
    cudaGetSymbolAddress((void**)&Wv16, g_Wv16);
    cudaGetSymbolAddress((void**)&Ws16, g_Ws16);
    cudaGetSymbolAddress((void**)&Qt, g_Qt16);
    cudaGetSymbolAddress((void**)&Kt, g_Kt16);
    cudaGetSymbolAddress((void**)&V, g_V16);
    cudaGetSymbolAddress((void**)&P, g_P);
    cudaGetSymbolAddress((void**)&RS, g_RS);

    static bool attr_done = false;
    if (!attr_done) {
        cudaFuncSetAttribute(tc_gemm_energy,
                             cudaFuncAttributeMaxDynamicSharedMemorySize, SMEMBYTES);
        cudaFuncSetAttribute(tc_gemm_proj,
                             cudaFuncAttributeMaxDynamicSharedMemorySize, SMEMBYTES);
        cudaFuncSetAttribute(tc_gemm_pv_skip,
                             cudaFuncAttributeMaxDynamicSharedMemorySize, SMEMBYTES);
        attr_done = true;
    }

    const float rscale = 0.04419417382415922f;  // 1/sqrt(512)
    const size_t sNC = (size_t)NN * CC;
    const size_t sMC = (size_t)MM * CC;

    // 0) transpose+cvt both inputs (1 launch); cvt weights + zero RS (1 launch)
    transpose_cvt2_kernel<<<dim3(UP_TILES + DN_TILES, 1, BB), 256>>>(
        pcd_up, pcd_down, Tup, Tdn);
    cvt4_kernel<<<dim3(CC * CC / 256, 5), 256>>>(
        Wq, Wk, Wv, Wskip, Wq16, Wk16, Wv16, Ws16, RS, CC * CC);

    // 1) Qt/Kt/V projections, one launch (192 tiles/batch)
    GDesc d0 = {Tup,  Wq16, Qt, CC, CC, CC, sNC, 0,   sNC, CC / 128, 2};
    GDesc d1 = {Tdn,  Wk16, Kt, CC, CC, CC, sMC, 0,   sMC, CC / 128, 2};
    GDesc d2 = {Wv16, Tdn,  V,  CC, CC, MM, 0,   sMC, sMC, MM / 128, 2};
    tc_gemm_proj<<<dim3(192, 1, BB), 256, SMEMBYTES>>>(d0, d1, d2);

    // 2) expE[n][m] = exp(rscale * Qt·Kt^T); row sums accumulated atomically
    tc_gemm_energy<<<dim3(MM / 128, NN / 128, BB), 256, SMEMBYTES>>>(
        Qt, Kt, P, RS, rscale);

    // 3) out[c][n] = (V·expE^T)/rowsum[n] + Wskip·Tup^T  (single fp32 write)
    tc_gemm_pv_skip<<<dim3(NN / 128, CC / 128, BB), 256, SMEMBYTES>>>(
        V, P, Ws16, Tup, RS, out);
}